// round 11
// baseline (speedup 1.0000x reference)
#include <cuda_runtime.h>
#include <cuda_fp16.h>
#include <stdint.h>
#include <math.h>
#include <float.h>

typedef unsigned int u32;

#define B_   2
#define S_   2048
#define H_   16
#define HD_  64
#define DM_  1024
#define M_   (B_ * S_)

// ---------------- device scratch (no allocations allowed) ------------------
__device__ __half g_Xhi[(size_t)M_ * DM_];
__device__ __half g_Xlo[(size_t)M_ * DM_];
__device__ __half g_Whi[(size_t)4 * DM_ * DM_];
__device__ __half g_Wlo[(size_t)4 * DM_ * DM_];
__device__ __half g_Qhi[(size_t)M_ * DM_];   // [b,h,s,d], pre-scaled by 0.125*log2(e)
__device__ __half g_Qlo[(size_t)M_ * DM_];
__device__ __half g_Khi[(size_t)M_ * DM_];
__device__ __half g_Klo[(size_t)M_ * DM_];
__device__ __half g_Vhi[(size_t)M_ * DM_];
__device__ __half g_AOhi[(size_t)M_ * DM_];
__device__ __half g_AOlo[(size_t)M_ * DM_];

// ---------------- PTX helpers ----------------------------------------------
__device__ __forceinline__ u32 s2u(const void* p)
{
    u32 a;
    asm("{ .reg .u64 t; cvta.to.shared.u64 t, %1; cvt.u32.u64 %0, t; }"
        : "=r"(a) : "l"(p));
    return a;
}

__device__ __forceinline__ void ldsm4(u32* r, u32 addr)
{
    asm volatile("ldmatrix.sync.aligned.m8n8.x4.shared.b16 {%0,%1,%2,%3},[%4];"
                 : "=r"(r[0]), "=r"(r[1]), "=r"(r[2]), "=r"(r[3]) : "r"(addr));
}

__device__ __forceinline__ void ldsm4t(u32* r, u32 addr)
{
    asm volatile("ldmatrix.sync.aligned.m8n8.x4.trans.shared.b16 {%0,%1,%2,%3},[%4];"
                 : "=r"(r[0]), "=r"(r[1]), "=r"(r[2]), "=r"(r[3]) : "r"(addr));
}

__device__ __forceinline__ void mma16816(float* c, const u32* a, const u32* b)
{
    asm volatile("mma.sync.aligned.m16n8k16.row.col.f32.f16.f16.f32 "
                 "{%0,%1,%2,%3},{%4,%5,%6,%7},{%8,%9},{%0,%1,%2,%3};"
                 : "+f"(c[0]), "+f"(c[1]), "+f"(c[2]), "+f"(c[3])
                 : "r"(a[0]), "r"(a[1]), "r"(a[2]), "r"(a[3]),
                   "r"(b[0]), "r"(b[1]));
}

__device__ __forceinline__ u32 packf2(float lo, float hi)
{
    u32 u;
    asm("cvt.rn.f16x2.f32 %0, %1, %2;" : "=r"(u) : "f"(hi), "f"(lo));
    return u;
}

__device__ __forceinline__ void cpa16(u32 saddr, const void* gaddr)
{
    asm volatile("cp.async.cg.shared.global [%0], [%1], 16;"
                 :: "r"(saddr), "l"(gaddr));
}

__device__ __forceinline__ void cp_commit()
{
    asm volatile("cp.async.commit_group;" ::: "memory");
}

__device__ __forceinline__ void cp_wait1()
{
    asm volatile("cp.async.wait_group 1;" ::: "memory");
}

__device__ __forceinline__ void cp_wait0()
{
    asm volatile("cp.async.wait_group 0;" ::: "memory");
}

// ---------------- fp32 -> fp16 hi/lo splitters ------------------------------
__device__ __forceinline__ void split4(const float* src, __half* dh, __half* dl, int i)
{
    float4 v = *(const float4*)&src[i];
    __half h0 = __float2half_rn(v.x);
    __half h1 = __float2half_rn(v.y);
    __half h2 = __float2half_rn(v.z);
    __half h3 = __float2half_rn(v.w);
    __half l0 = __float2half_rn(v.x - __half2float(h0));
    __half l1 = __float2half_rn(v.y - __half2float(h1));
    __half l2 = __float2half_rn(v.z - __half2float(h2));
    __half l3 = __float2half_rn(v.w - __half2float(h3));
    ((__half2*)&dh[i])[0] = __halves2half2(h0, h1);
    ((__half2*)&dh[i])[1] = __halves2half2(h2, h3);
    ((__half2*)&dl[i])[0] = __halves2half2(l0, l1);
    ((__half2*)&dl[i])[1] = __halves2half2(l2, l3);
}

__global__ __launch_bounds__(256) void split_x_kernel(const float* __restrict__ src)
{
    const int n = M_ * DM_;
    for (int i = (blockIdx.x * blockDim.x + threadIdx.x) * 4; i < n;
         i += gridDim.x * blockDim.x * 4) {
        split4(src, g_Xhi, g_Xlo, i);
    }
}

__global__ __launch_bounds__(256) void split_w_kernel(const float* __restrict__ w0,
                                                      const float* __restrict__ w1,
                                                      const float* __restrict__ w2,
                                                      const float* __restrict__ w3)
{
    const int which = blockIdx.y;
    const float* src = (which == 0) ? w0 : ((which == 1) ? w1 : ((which == 2) ? w2 : w3));
    __half* dh = g_Whi + (size_t)which * (DM_ * DM_);
    __half* dl = g_Wlo + (size_t)which * (DM_ * DM_);
    const int n = DM_ * DM_;
    for (int i = (blockIdx.x * blockDim.x + threadIdx.x) * 4; i < n;
         i += gridDim.x * blockDim.x * 4) {
        split4(src, dh, dl, i);
    }
}

// ---------------- fp16 hi/lo split GEMM, cp.async 2-stage, BK=32 ------------
// Y[m,n] = sum_k A[m,k] * W[n,k]; fp32 acc; combos hh + hl + lh.
// Block 128x128, 8 warps (2m x 4n), warp tile 64x32. Dynamic smem 80 KB.
#define GLD   40
#define GARR  (128 * GLD * 2)          // bytes per array per stage = 10240
#define GOFF_ALO  GARR
#define GOFF_BHI  (2 * GARR)
#define GOFF_BLO  (3 * GARR)
#define GSSB  (4 * GARR)               // stage stride bytes = 40960
#define GSMEM (2 * GSSB)               // 81920

__device__ __forceinline__ void gemm_stage_load(u32 sb, int st, int tid,
                                                int m0, int n0, int k0,
                                                const __half* Ahi, const __half* Alo,
                                                const __half* Bhi, const __half* Blo)
{
#pragma unroll
    for (int u = 0; u < 2; u++) {
        const int id  = tid * 2 + u;      // 0..511
        const int row = id >> 2;          // 0..127
        const int c   = (id & 3) * 8;     // 0,8,16,24
        const u32 so  = sb + (u32)(st * GSSB) + (u32)(row * GLD + c) * 2u;
        cpa16(so,            &Ahi[(size_t)(m0 + row) * DM_ + k0 + c]);
        cpa16(so + GOFF_ALO, &Alo[(size_t)(m0 + row) * DM_ + k0 + c]);
        cpa16(so + GOFF_BHI, &Bhi[(size_t)(n0 + row) * DM_ + k0 + c]);
        cpa16(so + GOFF_BLO, &Blo[(size_t)(n0 + row) * DM_ + k0 + c]);
    }
}

template <int MODE>
__global__ __launch_bounds__(256) void hgemm_kernel(const int* __restrict__ tpos,
                                                    float* __restrict__ outp)
{
    extern __shared__ __half gsm[];

    const int z = (MODE == 0) ? blockIdx.z : 3;
    const __half* Ahi = (MODE == 0) ? g_Xhi : g_AOhi;
    const __half* Alo = (MODE == 0) ? g_Xlo : g_AOlo;
    const __half* Bhi = g_Whi + (size_t)z * DM_ * DM_;
    const __half* Blo = g_Wlo + (size_t)z * DM_ * DM_;

    const int tid  = threadIdx.x;
    const int lane = tid & 31;
    const int wid  = tid >> 5;
    const int wm   = wid >> 2;
    const int wn   = wid & 3;
    const int m0   = blockIdx.y * 128;
    const int n0   = blockIdx.x * 128;

    const u32 sb = s2u(gsm);

    float acc[4][4][4];
#pragma unroll
    for (int i = 0; i < 4; i++) {
#pragma unroll
        for (int j = 0; j < 4; j++) {
            acc[i][j][0] = 0.0f; acc[i][j][1] = 0.0f;
            acc[i][j][2] = 0.0f; acc[i][j][3] = 0.0f;
        }
    }

    const int arow = wm * 64 + (lane & 15);
    const int acol = (lane >> 4) << 3;
    const int brow = wn * 32 + (lane & 7) + ((lane & 16) ? 8 : 0);
    const int bcol = (lane & 8) ? 8 : 0;

    gemm_stage_load(sb, 0, tid, m0, n0, 0, Ahi, Alo, Bhi, Blo);
    cp_commit();

    for (int it = 0; it < 32; it++) {
        if (it < 31) {
            gemm_stage_load(sb, (it + 1) & 1, tid, m0, n0, (it + 1) * 32,
                            Ahi, Alo, Bhi, Blo);
            cp_commit();
            cp_wait1();
        } else {
            cp_wait0();
        }
        __syncthreads();

        const u32 tb = sb + (u32)((it & 1) * GSSB);

#pragma unroll
        for (int ks = 0; ks < 32; ks += 16) {
            u32 ah[4][4];
            u32 al[4][4];
            u32 bh2[2][4];
            u32 bl2[2][4];
#pragma unroll
            for (int i = 0; i < 4; i++) {
                const u32 off = (u32)((arow + i * 16) * GLD + ks + acol) * 2u;
                ldsm4(ah[i], tb + off);
                ldsm4(al[i], tb + GOFF_ALO + off);
            }
#pragma unroll
            for (int jn = 0; jn < 2; jn++) {
                const u32 off = (u32)((brow + jn * 16) * GLD + ks + bcol) * 2u;
                ldsm4(bh2[jn], tb + GOFF_BHI + off);
                ldsm4(bl2[jn], tb + GOFF_BLO + off);
            }
#pragma unroll
            for (int i = 0; i < 4; i++) {
#pragma unroll
                for (int j = 0; j < 4; j++) {
                    const u32* Bh = &bh2[j >> 1][(j & 1) * 2];
                    const u32* Bl = &bl2[j >> 1][(j & 1) * 2];
                    mma16816(acc[i][j], ah[i], Bh);
                    mma16816(acc[i][j], ah[i], Bl);
                    mma16816(acc[i][j], al[i], Bh);
                }
            }
        }
        __syncthreads();   // all reads of this stage done before it is reloaded
    }

    const int g = lane >> 2;
    const int t = lane & 3;

    if (MODE == 1) {
#pragma unroll
        for (int i = 0; i < 4; i++) {
            const int m = m0 + wm * 64 + i * 16 + g;
#pragma unroll
            for (int j = 0; j < 4; j++) {
                const int n = n0 + wn * 32 + j * 8 + t * 2;
                *(float2*)&outp[(size_t)m * DM_ + n] = make_float2(acc[i][j][0], acc[i][j][1]);
                *(float2*)&outp[(size_t)(m + 8) * DM_ + n] = make_float2(acc[i][j][2], acc[i][j][3]);
            }
        }
        return;
    }

    // MODE 0 epilogue: RoPE (z<2), scale (z==0 folds 1/sqrt(hd)*log2e), split.
    // V (z==2): hi only — the lo correction is dropped from P*V.
    __half* Dhi = (z == 0) ? g_Qhi : ((z == 1) ? g_Khi : g_Vhi);
    __half* Dlo = (z == 0) ? g_Qlo : g_Klo;   // unused for z==2
    const bool rope = (z < 2);
    const float c_ln = 0.14391156931f;          // ln(10000)/64
    const float qscale = 0.18033688011f;        // 0.125 * log2(e)
#pragma unroll
    for (int i = 0; i < 4; i++) {
#pragma unroll
        for (int rr = 0; rr < 2; rr++) {
            const int m = m0 + wm * 64 + i * 16 + g + rr * 8;
            const int bb = m >> 11;
            const int ss = m & (S_ - 1);
            const float pos = (float)tpos[ss];
#pragma unroll
            for (int j = 0; j < 4; j++) {
                const int n = n0 + wn * 32 + j * 8 + t * 2;
                const int hh = n >> 6;
                const int dd = n & 63;
                float v0 = acc[i][j][rr * 2 + 0];
                float v1 = acc[i][j][rr * 2 + 1];
                if (rope) {
                    const float inv = expf(-(float)dd * c_ln);
                    float sn, cs;
                    sincosf(pos * inv, &sn, &cs);
                    const float r1 = v0 * cs - v1 * sn;
                    const float r2 = v0 * sn + v1 * cs;
                    v0 = r1;
                    v1 = r2;
                }
                if (z == 0) {
                    v0 *= qscale;
                    v1 *= qscale;
                }
                const __half p0 = __float2half_rn(v0);
                const __half p1 = __float2half_rn(v1);
                const size_t ofs = ((size_t)(bb * H_ + hh) * S_ + ss) * HD_ + dd;
                *(__half2*)&Dhi[ofs] = __halves2half2(p0, p1);
                if (z < 2) {
                    const __half e0 = __float2half_rn(v0 - __half2float(p0));
                    const __half e1 = __float2half_rn(v1 - __half2float(p1));
                    *(__half2*)&Dlo[ofs] = __halves2half2(e0, e1);
                }
            }
        }
    }
}

// ---------------- mma flash attention (causal), 64-key cp.async stages ------
// grid=(S/64, B*H), block=128 (4 warps). Warp w owns q rows [w*16, w*16+16).
// Stage: [Kh 64xALD][Kl][Vh], AARR bytes each; 2 stages, dynamic smem 55 KB.
#define ALD   72
#define AARR  (64 * ALD * 2)        // 9216 bytes
#define ASTG  (3 * AARR)            // 27648 bytes per stage
#define ASMEM (2 * ASTG)            // 55296

__device__ __forceinline__ void attn_stage_load(u32 sb, int st, int tid,
                                                size_t gbase, int k0)
{
#pragma unroll
    for (int u = 0; u < 4; u++) {
        const int id  = tid * 4 + u;      // 0..511
        const int row = id >> 3;          // 0..63
        const int c   = (id & 7) * 8;     // 0..56
        const size_t go = gbase + (size_t)(k0 + row) * HD_ + c;
        const u32 so = sb + (u32)(st * ASTG) + (u32)(row * ALD + c) * 2u;
        cpa16(so,            &g_Khi[go]);
        cpa16(so + AARR,     &g_Klo[go]);
        cpa16(so + 2 * AARR, &g_Vhi[go]);
    }
}

__global__ __launch_bounds__(128) void attn_kernel()
{
    extern __shared__ __half asm_[];

    const int tid  = threadIdx.x;
    const int lane = tid & 31;
    const int wid  = tid >> 5;
    const int q0   = (gridDim.x - 1 - blockIdx.x) * 64;   // long blocks first
    const int bh   = blockIdx.y;
    const size_t gbase = (size_t)bh * S_ * HD_;

    const u32 sb = s2u(asm_);

    // ---- stage Q tile (hi at 0, lo at AARR) and pull fragments ----
    for (int u = tid; u < 512; u += 128) {
        const int row = u >> 3;
        const int c   = (u & 7) * 8;
        *(int4*)&asm_[row * ALD + c] =
            *(const int4*)&g_Qhi[gbase + (size_t)(q0 + row) * HD_ + c];
        *(int4*)&asm_[64 * ALD + row * ALD + c] =
            *(const int4*)&g_Qlo[gbase + (size_t)(q0 + row) * HD_ + c];
    }
    __syncthreads();

    u32 qh[4][4];
    u32 ql[4][4];
    {
        const int row = wid * 16 + (lane & 15);
        const int col = (lane >> 4) << 3;
#pragma unroll
        for (int kd = 0; kd < 4; kd++) {
            const u32 off = (u32)(row * ALD + kd * 16 + col) * 2u;
            ldsm4(qh[kd], sb + off);
            ldsm4(ql[kd], sb + (u32)AARR + off);
        }
    }
    __syncthreads();

    float o[8][4];
#pragma unroll
    for (int j = 0; j < 8; j++) {
        o[j][0] = 0.0f; o[j][1] = 0.0f; o[j][2] = 0.0f; o[j][3] = 0.0f;
    }
    float mrow0 = -1e30f;
    float mrow1 = -1e30f;
    float lrow0 = 0.0f;
    float lrow1 = 0.0f;

    const int g = lane >> 2;
    const int t = lane & 3;
    const int browK = (lane & 7) + ((lane & 16) ? 8 : 0);
    const int bcolK = (lane & 8) ? 8 : 0;
    const int vrow  = lane & 15;
    const int vcol  = (lane >> 4) << 3;

    const int ntiles = q0 / 64 + 1;     // 64-key tiles, keys 0 .. q0+63

    attn_stage_load(sb, 0, tid, gbase, 0);
    cp_commit();

    for (int it = 0; it < ntiles; it++) {
        const int k0 = it * 64;
        if (it + 1 < ntiles) {
            attn_stage_load(sb, (it + 1) & 1, tid, gbase, (it + 1) * 64);
            cp_commit();
            cp_wait1();
        } else {
            cp_wait0();
        }
        __syncthreads();

        const u32 tb = sb + (u32)((it & 1) * ASTG);

        // S = Q K^T over 64 keys (Q pre-scaled by 0.125*log2e -> base-2 space)
        float s[8][4];
#pragma unroll
        for (int j = 0; j < 8; j++) {
            s[j][0] = 0.0f; s[j][1] = 0.0f; s[j][2] = 0.0f; s[j][3] = 0.0f;
        }
#pragma unroll
        for (int kd = 0; kd < 4; kd++) {
#pragma unroll
            for (int jn = 0; jn < 4; jn++) {
                u32 kh4[4];
                u32 kl4[4];
                const u32 off = (u32)((jn * 16 + browK) * ALD + kd * 16 + bcolK) * 2u;
                ldsm4(kh4, tb + off);
                ldsm4(kl4, tb + (u32)AARR + off);
                mma16816(s[jn * 2 + 0], qh[kd], &kh4[0]);
                mma16816(s[jn * 2 + 0], qh[kd], &kl4[0]);
                mma16816(s[jn * 2 + 0], ql[kd], &kh4[0]);
                mma16816(s[jn * 2 + 1], qh[kd], &kh4[2]);
                mma16816(s[jn * 2 + 1], qh[kd], &kl4[2]);
                mma16816(s[jn * 2 + 1], ql[kd], &kh4[2]);
            }
        }

        // causal mask (diagonal tile only)
        if (k0 == q0) {
#pragma unroll
            for (int j = 0; j < 8; j++) {
#pragma unroll
                for (int e = 0; e < 4; e++) {
                    const int kidx = k0 + j * 8 + t * 2 + (e & 1);
                    const int qidx = q0 + wid * 16 + g + (e >> 1) * 8;
                    if (kidx > qidx) s[j][e] = -1e30f;
                }
            }
        }

        // online softmax (base 2), row pair (g, g+8)
        {
            float mx0 = -1e30f;
            float mx1 = -1e30f;
#pragma unroll
            for (int j = 0; j < 8; j++) {
                mx0 = fmaxf(mx0, fmaxf(s[j][0], s[j][1]));
                mx1 = fmaxf(mx1, fmaxf(s[j][2], s[j][3]));
            }
            mx0 = fmaxf(mx0, __shfl_xor_sync(0xffffffffu, mx0, 1));
            mx0 = fmaxf(mx0, __shfl_xor_sync(0xffffffffu, mx0, 2));
            mx1 = fmaxf(mx1, __shfl_xor_sync(0xffffffffu, mx1, 1));
            mx1 = fmaxf(mx1, __shfl_xor_sync(0xffffffffu, mx1, 2));

            const float mn0 = fmaxf(mrow0, mx0);
            const float mn1 = fmaxf(mrow1, mx1);
            const float al0 = exp2f(mrow0 - mn0);
            const float al1 = exp2f(mrow1 - mn1);
            float sum0 = 0.0f;
            float sum1 = 0.0f;
#pragma unroll
            for (int j = 0; j < 8; j++) {
                const float p0 = exp2f(s[j][0] - mn0);
                const float p1 = exp2f(s[j][1] - mn0);
                const float p2 = exp2f(s[j][2] - mn1);
                const float p3 = exp2f(s[j][3] - mn1);
                s[j][0] = p0;
                s[j][1] = p1;
                s[j][2] = p2;
                s[j][3] = p3;
                sum0 += p0 + p1;
                sum1 += p2 + p3;
            }
            sum0 += __shfl_xor_sync(0xffffffffu, sum0, 1);
            sum0 += __shfl_xor_sync(0xffffffffu, sum0, 2);
            sum1 += __shfl_xor_sync(0xffffffffu, sum1, 1);
            sum1 += __shfl_xor_sync(0xffffffffu, sum1, 2);
            lrow0 = lrow0 * al0 + sum0;
            lrow1 = lrow1 * al1 + sum1;
            mrow0 = mn0;
            mrow1 = mn1;
#pragma unroll
            for (int j = 0; j < 8; j++) {
                o[j][0] *= al0;
                o[j][1] *= al0;
                o[j][2] *= al1;
                o[j][3] *= al1;
            }
        }

        // O += P @ V  (P fp16, V hi only), 64 keys
#pragma unroll
        for (int kk = 0; kk < 4; kk++) {
            u32 pa[4];
            pa[0] = packf2(s[2 * kk + 0][0], s[2 * kk + 0][1]);
            pa[1] = packf2(s[2 * kk + 0][2], s[2 * kk + 0][3]);
            pa[2] = packf2(s[2 * kk + 1][0], s[2 * kk + 1][1]);
            pa[3] = packf2(s[2 * kk + 1][2], s[2 * kk + 1][3]);
#pragma unroll
            for (int jd = 0; jd < 4; jd++) {
                u32 vh4[4];
                const u32 off = (u32)((kk * 16 + vrow) * ALD + jd * 16 + vcol) * 2u;
                ldsm4t(vh4, tb + (u32)(2 * AARR) + off);
                mma16816(o[jd * 2 + 0], pa, &vh4[0]);
                mma16816(o[jd * 2 + 1], pa, &vh4[2]);
            }
        }
        __syncthreads();
    }

    // epilogue: normalize, hi/lo split, store to AO
    const int bb = bh >> 4;
    const int hh = bh & 15;
    const float il0 = 1.0f / lrow0;
    const float il1 = 1.0f / lrow1;
    const int qa = q0 + wid * 16 + g;
    const size_t rowa = ((size_t)bb * S_ + qa) * DM_ + hh * HD_;
    const size_t rowb = ((size_t)bb * S_ + qa + 8) * DM_ + hh * HD_;
#pragma unroll
    for (int j = 0; j < 8; j++) {
        const int dd = j * 8 + t * 2;
        const float v0 = o[j][0] * il0;
        const float v1 = o[j][1] * il0;
        const float v2 = o[j][2] * il1;
        const float v3 = o[j][3] * il1;
        const __half p0 = __float2half_rn(v0);
        const __half p1 = __float2half_rn(v1);
        const __half p2 = __float2half_rn(v2);
        const __half p3 = __float2half_rn(v3);
        const __half e0 = __float2half_rn(v0 - __half2float(p0));
        const __half e1 = __float2half_rn(v1 - __half2float(p1));
        const __half e2 = __float2half_rn(v2 - __half2float(p2));
        const __half e3 = __float2half_rn(v3 - __half2float(p3));
        *(__half2*)&g_AOhi[rowa + dd] = __halves2half2(p0, p1);
        *(__half2*)&g_AOlo[rowa + dd] = __halves2half2(e0, e1);
        *(__half2*)&g_AOhi[rowb + dd] = __halves2half2(p2, p3);
        *(__half2*)&g_AOlo[rowb + dd] = __halves2half2(e2, e3);
    }
}

// ---------------------------------------------------------------------------
extern "C" void kernel_launch(void* const* d_in, const int* in_sizes, int n_in,
                              void* d_out, int out_size)
{
    const float* x  = (const float*)d_in[0];
    const int*   tp = (const int*)d_in[1];
    const float* Wq = (const float*)d_in[2];
    const float* Wk = (const float*)d_in[3];
    const float* Wv = (const float*)d_in[4];
    const float* Wo = (const float*)d_in[5];
    float* out = (float*)d_out;

    static int attr_done = 0;
    if (!attr_done) {
        cudaFuncSetAttribute(hgemm_kernel<0>,
                             cudaFuncAttributeMaxDynamicSharedMemorySize, GSMEM);
        cudaFuncSetAttribute(hgemm_kernel<1>,
                             cudaFuncAttributeMaxDynamicSharedMemorySize, GSMEM);
        cudaFuncSetAttribute(attn_kernel,
                             cudaFuncAttributeMaxDynamicSharedMemorySize, ASMEM);
        attr_done = 1;
    }

    split_x_kernel<<<512, 256>>>(x);
    {
        dim3 grid(128, 4);
        split_w_kernel<<<grid, 256>>>(Wq, Wk, Wv, Wo);
    }
    {
        dim3 grid(DM_ / 128, M_ / 128, 3);
        hgemm_kernel<0><<<grid, 256, GSMEM>>>(tp, nullptr);
    }
    {
        dim3 grid(S_ / 64, B_ * H_);
        attn_kernel<<<grid, 128, ASMEM>>>();
    }
    {
        dim3 grid(DM_ / 128, M_ / 128, 1);
        hgemm_kernel<1><<<grid, 256, GSMEM>>>(nullptr, out);
    }
}

// round 12
// speedup vs baseline: 1.0710x; 1.0710x over previous
#include <cuda_runtime.h>
#include <cuda_fp16.h>
#include <stdint.h>
#include <math.h>
#include <float.h>

typedef unsigned int u32;

#define B_   2
#define S_   2048
#define H_   16
#define HD_  64
#define DM_  1024
#define M_   (B_ * S_)

// ---------------- device scratch (no allocations allowed) ------------------
__device__ __half g_Xhi[(size_t)M_ * DM_];
__device__ __half g_Xlo[(size_t)M_ * DM_];
__device__ __half g_Whi[(size_t)4 * DM_ * DM_];
__device__ __half g_Wlo[(size_t)4 * DM_ * DM_];
__device__ __half g_Qhi[(size_t)M_ * DM_];   // [b,h,s,d], pre-scaled by 0.125*log2(e)
__device__ __half g_Qlo[(size_t)M_ * DM_];
__device__ __half g_Khi[(size_t)M_ * DM_];
__device__ __half g_Klo[(size_t)M_ * DM_];
__device__ __half g_Vhi[(size_t)M_ * DM_];
__device__ __half g_AOhi[(size_t)M_ * DM_];
__device__ __half g_AOlo[(size_t)M_ * DM_];

// ---------------- PTX helpers ----------------------------------------------
__device__ __forceinline__ u32 s2u(const void* p)
{
    u32 a;
    asm("{ .reg .u64 t; cvta.to.shared.u64 t, %1; cvt.u32.u64 %0, t; }"
        : "=r"(a) : "l"(p));
    return a;
}

__device__ __forceinline__ void ldsm4(u32* r, u32 addr)
{
    asm volatile("ldmatrix.sync.aligned.m8n8.x4.shared.b16 {%0,%1,%2,%3},[%4];"
                 : "=r"(r[0]), "=r"(r[1]), "=r"(r[2]), "=r"(r[3]) : "r"(addr));
}

__device__ __forceinline__ void ldsm4t(u32* r, u32 addr)
{
    asm volatile("ldmatrix.sync.aligned.m8n8.x4.trans.shared.b16 {%0,%1,%2,%3},[%4];"
                 : "=r"(r[0]), "=r"(r[1]), "=r"(r[2]), "=r"(r[3]) : "r"(addr));
}

__device__ __forceinline__ void mma16816(float* c, const u32* a, const u32* b)
{
    asm volatile("mma.sync.aligned.m16n8k16.row.col.f32.f16.f16.f32 "
                 "{%0,%1,%2,%3},{%4,%5,%6,%7},{%8,%9},{%0,%1,%2,%3};"
                 : "+f"(c[0]), "+f"(c[1]), "+f"(c[2]), "+f"(c[3])
                 : "r"(a[0]), "r"(a[1]), "r"(a[2]), "r"(a[3]),
                   "r"(b[0]), "r"(b[1]));
}

__device__ __forceinline__ u32 packf2(float lo, float hi)
{
    u32 u;
    asm("cvt.rn.f16x2.f32 %0, %1, %2;" : "=r"(u) : "f"(hi), "f"(lo));
    return u;
}

__device__ __forceinline__ void cpa16(u32 saddr, const void* gaddr)
{
    asm volatile("cp.async.cg.shared.global [%0], [%1], 16;"
                 :: "r"(saddr), "l"(gaddr));
}

__device__ __forceinline__ void cp_commit()
{
    asm volatile("cp.async.commit_group;" ::: "memory");
}

__device__ __forceinline__ void cp_wait1()
{
    asm volatile("cp.async.wait_group 1;" ::: "memory");
}

__device__ __forceinline__ void cp_wait0()
{
    asm volatile("cp.async.wait_group 0;" ::: "memory");
}

// ---------------- fp32 -> fp16 hi/lo splitters ------------------------------
__device__ __forceinline__ void split4(const float* src, __half* dh, __half* dl, int i)
{
    float4 v = *(const float4*)&src[i];
    __half h0 = __float2half_rn(v.x);
    __half h1 = __float2half_rn(v.y);
    __half h2 = __float2half_rn(v.z);
    __half h3 = __float2half_rn(v.w);
    __half l0 = __float2half_rn(v.x - __half2float(h0));
    __half l1 = __float2half_rn(v.y - __half2float(h1));
    __half l2 = __float2half_rn(v.z - __half2float(h2));
    __half l3 = __float2half_rn(v.w - __half2float(h3));
    ((__half2*)&dh[i])[0] = __halves2half2(h0, h1);
    ((__half2*)&dh[i])[1] = __halves2half2(h2, h3);
    ((__half2*)&dl[i])[0] = __halves2half2(l0, l1);
    ((__half2*)&dl[i])[1] = __halves2half2(l2, l3);
}

__global__ __launch_bounds__(256) void split_x_kernel(const float* __restrict__ src)
{
    const int n = M_ * DM_;
    for (int i = (blockIdx.x * blockDim.x + threadIdx.x) * 4; i < n;
         i += gridDim.x * blockDim.x * 4) {
        split4(src, g_Xhi, g_Xlo, i);
    }
}

__global__ __launch_bounds__(256) void split_w_kernel(const float* __restrict__ w0,
                                                      const float* __restrict__ w1,
                                                      const float* __restrict__ w2,
                                                      const float* __restrict__ w3)
{
    const int which = blockIdx.y;
    const float* src = (which == 0) ? w0 : ((which == 1) ? w1 : ((which == 2) ? w2 : w3));
    __half* dh = g_Whi + (size_t)which * (DM_ * DM_);
    __half* dl = g_Wlo + (size_t)which * (DM_ * DM_);
    const int n = DM_ * DM_;
    for (int i = (blockIdx.x * blockDim.x + threadIdx.x) * 4; i < n;
         i += gridDim.x * blockDim.x * 4) {
        split4(src, dh, dl, i);
    }
}

// ---------------- fp16 hi/lo split GEMM, cp.async 2-stage, BK=32 ------------
// Y[m,n] = sum_k A[m,k] * W[n,k]; fp32 acc; combos hh + hl + lh.
// Block 128x128, 8 warps (2m x 4n), warp tile 64x32. Dynamic smem 80 KB.
#define GLD   40
#define GARR  (128 * GLD * 2)          // bytes per array per stage = 10240
#define GOFF_ALO  GARR
#define GOFF_BHI  (2 * GARR)
#define GOFF_BLO  (3 * GARR)
#define GSSB  (4 * GARR)               // stage stride bytes = 40960
#define GSMEM (2 * GSSB)               // 81920

__device__ __forceinline__ void gemm_stage_load(u32 sb, int st, int tid,
                                                int m0, int n0, int k0,
                                                const __half* Ahi, const __half* Alo,
                                                const __half* Bhi, const __half* Blo)
{
#pragma unroll
    for (int u = 0; u < 2; u++) {
        const int id  = tid * 2 + u;      // 0..511
        const int row = id >> 2;          // 0..127
        const int c   = (id & 3) * 8;     // 0,8,16,24
        const u32 so  = sb + (u32)(st * GSSB) + (u32)(row * GLD + c) * 2u;
        cpa16(so,            &Ahi[(size_t)(m0 + row) * DM_ + k0 + c]);
        cpa16(so + GOFF_ALO, &Alo[(size_t)(m0 + row) * DM_ + k0 + c]);
        cpa16(so + GOFF_BHI, &Bhi[(size_t)(n0 + row) * DM_ + k0 + c]);
        cpa16(so + GOFF_BLO, &Blo[(size_t)(n0 + row) * DM_ + k0 + c]);
    }
}

template <int MODE>
__global__ __launch_bounds__(256) void hgemm_kernel(const int* __restrict__ tpos,
                                                    float* __restrict__ outp)
{
    extern __shared__ __half gsm[];

    const int z = (MODE == 0) ? blockIdx.z : 3;
    const __half* Ahi = (MODE == 0) ? g_Xhi : g_AOhi;
    const __half* Alo = (MODE == 0) ? g_Xlo : g_AOlo;
    const __half* Bhi = g_Whi + (size_t)z * DM_ * DM_;
    const __half* Blo = g_Wlo + (size_t)z * DM_ * DM_;

    const int tid  = threadIdx.x;
    const int lane = tid & 31;
    const int wid  = tid >> 5;
    const int wm   = wid >> 2;
    const int wn   = wid & 3;
    const int m0   = blockIdx.y * 128;
    const int n0   = blockIdx.x * 128;

    const u32 sb = s2u(gsm);

    float acc[4][4][4];
#pragma unroll
    for (int i = 0; i < 4; i++) {
#pragma unroll
        for (int j = 0; j < 4; j++) {
            acc[i][j][0] = 0.0f; acc[i][j][1] = 0.0f;
            acc[i][j][2] = 0.0f; acc[i][j][3] = 0.0f;
        }
    }

    const int arow = wm * 64 + (lane & 15);
    const int acol = (lane >> 4) << 3;
    const int brow = wn * 32 + (lane & 7) + ((lane & 16) ? 8 : 0);
    const int bcol = (lane & 8) ? 8 : 0;

    gemm_stage_load(sb, 0, tid, m0, n0, 0, Ahi, Alo, Bhi, Blo);
    cp_commit();

    for (int it = 0; it < 32; it++) {
        if (it < 31) {
            gemm_stage_load(sb, (it + 1) & 1, tid, m0, n0, (it + 1) * 32,
                            Ahi, Alo, Bhi, Blo);
            cp_commit();
            cp_wait1();
        } else {
            cp_wait0();
        }
        __syncthreads();

        const u32 tb = sb + (u32)((it & 1) * GSSB);

#pragma unroll
        for (int ks = 0; ks < 32; ks += 16) {
            u32 ah[4][4];
            u32 al[4][4];
            u32 bh2[2][4];
            u32 bl2[2][4];
#pragma unroll
            for (int i = 0; i < 4; i++) {
                const u32 off = (u32)((arow + i * 16) * GLD + ks + acol) * 2u;
                ldsm4(ah[i], tb + off);
                ldsm4(al[i], tb + GOFF_ALO + off);
            }
#pragma unroll
            for (int jn = 0; jn < 2; jn++) {
                const u32 off = (u32)((brow + jn * 16) * GLD + ks + bcol) * 2u;
                ldsm4(bh2[jn], tb + GOFF_BHI + off);
                ldsm4(bl2[jn], tb + GOFF_BLO + off);
            }
#pragma unroll
            for (int i = 0; i < 4; i++) {
#pragma unroll
                for (int j = 0; j < 4; j++) {
                    const u32* Bh = &bh2[j >> 1][(j & 1) * 2];
                    const u32* Bl = &bl2[j >> 1][(j & 1) * 2];
                    mma16816(acc[i][j], ah[i], Bh);
                    mma16816(acc[i][j], ah[i], Bl);
                    mma16816(acc[i][j], al[i], Bh);
                }
            }
        }
        __syncthreads();   // all reads of this stage done before it is reloaded
    }

    const int g = lane >> 2;
    const int t = lane & 3;

    if (MODE == 1) {
#pragma unroll
        for (int i = 0; i < 4; i++) {
            const int m = m0 + wm * 64 + i * 16 + g;
#pragma unroll
            for (int j = 0; j < 4; j++) {
                const int n = n0 + wn * 32 + j * 8 + t * 2;
                *(float2*)&outp[(size_t)m * DM_ + n] = make_float2(acc[i][j][0], acc[i][j][1]);
                *(float2*)&outp[(size_t)(m + 8) * DM_ + n] = make_float2(acc[i][j][2], acc[i][j][3]);
            }
        }
        return;
    }

    // MODE 0 epilogue: RoPE (z<2), scale (z==0 folds 1/sqrt(hd)*log2e), split.
    // V (z==2): hi only — the lo correction is dropped from P*V.
    __half* Dhi = (z == 0) ? g_Qhi : ((z == 1) ? g_Khi : g_Vhi);
    __half* Dlo = (z == 0) ? g_Qlo : g_Klo;   // unused for z==2
    const bool rope = (z < 2);
    const float c_ln = 0.14391156931f;          // ln(10000)/64
    const float qscale = 0.18033688011f;        // 0.125 * log2(e)
#pragma unroll
    for (int i = 0; i < 4; i++) {
#pragma unroll
        for (int rr = 0; rr < 2; rr++) {
            const int m = m0 + wm * 64 + i * 16 + g + rr * 8;
            const int bb = m >> 11;
            const int ss = m & (S_ - 1);
            const float pos = (float)tpos[ss];
#pragma unroll
            for (int j = 0; j < 4; j++) {
                const int n = n0 + wn * 32 + j * 8 + t * 2;
                const int hh = n >> 6;
                const int dd = n & 63;
                float v0 = acc[i][j][rr * 2 + 0];
                float v1 = acc[i][j][rr * 2 + 1];
                if (rope) {
                    const float inv = expf(-(float)dd * c_ln);
                    float sn, cs;
                    sincosf(pos * inv, &sn, &cs);
                    const float r1 = v0 * cs - v1 * sn;
                    const float r2 = v0 * sn + v1 * cs;
                    v0 = r1;
                    v1 = r2;
                }
                if (z == 0) {
                    v0 *= qscale;
                    v1 *= qscale;
                }
                const __half p0 = __float2half_rn(v0);
                const __half p1 = __float2half_rn(v1);
                const size_t ofs = ((size_t)(bb * H_ + hh) * S_ + ss) * HD_ + dd;
                *(__half2*)&Dhi[ofs] = __halves2half2(p0, p1);
                if (z < 2) {
                    const __half e0 = __float2half_rn(v0 - __half2float(p0));
                    const __half e1 = __float2half_rn(v1 - __half2float(p1));
                    *(__half2*)&Dlo[ofs] = __halves2half2(e0, e1);
                }
            }
        }
    }
}

// ---------------- mma flash attention (causal), cp.async double-buffered ----
// grid=(S/64, B*H), block=128 (4 warps). Warp w owns q rows [w*16, w*16+16).
// 32-key tiles; stage = [Kh][Kl][Vh] (27.6 KB static total). Base-2 softmax.
#define ALD  72
#define AARR (32 * ALD * 2)        // 4608 bytes
#define ASTG (3 * AARR)            // 13824 bytes per stage

__device__ __forceinline__ void attn_stage_load(u32 sb, int st, int tid,
                                                size_t gbase, int k0)
{
#pragma unroll
    for (int u = 0; u < 2; u++) {
        const int id  = tid * 2 + u;      // 0..255
        const int row = id >> 3;          // 0..31
        const int c   = (id & 7) * 8;     // 0..56
        const size_t go = gbase + (size_t)(k0 + row) * HD_ + c;
        const u32 so = sb + (u32)(st * ASTG) + (u32)(row * ALD + c) * 2u;
        cpa16(so,            &g_Khi[go]);
        cpa16(so + AARR,     &g_Klo[go]);
        cpa16(so + 2 * AARR, &g_Vhi[go]);
    }
}

__global__ __launch_bounds__(128) void attn_kernel()
{
    __shared__ __half smem[2 * ASTG / 2];   // 27648 bytes

    const int tid  = threadIdx.x;
    const int lane = tid & 31;
    const int wid  = tid >> 5;
    const int q0   = (gridDim.x - 1 - blockIdx.x) * 64;   // long blocks first
    const int bh   = blockIdx.y;
    const size_t gbase = (size_t)bh * S_ * HD_;

    const u32 sb = s2u(smem);

    // ---- stage Q tile (hi at 0, lo at 64*ALD) and pull fragments ----
    for (int u = tid; u < 512; u += 128) {
        const int row = u >> 3;
        const int c   = (u & 7) * 8;
        *(int4*)&smem[row * ALD + c] =
            *(const int4*)&g_Qhi[gbase + (size_t)(q0 + row) * HD_ + c];
        *(int4*)&smem[64 * ALD + row * ALD + c] =
            *(const int4*)&g_Qlo[gbase + (size_t)(q0 + row) * HD_ + c];
    }
    __syncthreads();

    u32 qh[4][4];
    u32 ql[4][4];
    {
        const int row = wid * 16 + (lane & 15);
        const int col = (lane >> 4) << 3;
        const u32 qlo_off = (u32)(64 * ALD) * 2u;
#pragma unroll
        for (int kd = 0; kd < 4; kd++) {
            const u32 off = (u32)(row * ALD + kd * 16 + col) * 2u;
            ldsm4(qh[kd], sb + off);
            ldsm4(ql[kd], sb + qlo_off + off);
        }
    }
    __syncthreads();

    float o[8][4];
#pragma unroll
    for (int j = 0; j < 8; j++) {
        o[j][0] = 0.0f; o[j][1] = 0.0f; o[j][2] = 0.0f; o[j][3] = 0.0f;
    }
    float mrow0 = -1e30f;
    float mrow1 = -1e30f;
    float lrow0 = 0.0f;
    float lrow1 = 0.0f;

    const int g = lane >> 2;
    const int t = lane & 3;
    const int browK = (lane & 7) + ((lane & 16) ? 8 : 0);
    const int bcolK = (lane & 8) ? 8 : 0;
    const int vrow  = lane & 15;
    const int vcol  = (lane >> 4) << 3;

    const int ntiles = q0 / 32 + 2;     // keys 0 .. q0+63

    attn_stage_load(sb, 0, tid, gbase, 0);
    cp_commit();

    for (int it = 0; it < ntiles; it++) {
        const int k0 = it * 32;
        if (it + 1 < ntiles) {
            attn_stage_load(sb, (it + 1) & 1, tid, gbase, (it + 1) * 32);
            cp_commit();
            cp_wait1();
        } else {
            cp_wait0();
        }
        __syncthreads();

        const u32 tb = sb + (u32)((it & 1) * ASTG);

        // S = Q K^T over 32 keys (Q pre-scaled by 0.125*log2e -> base-2 space)
        float s[4][4];
#pragma unroll
        for (int j = 0; j < 4; j++) {
            s[j][0] = 0.0f; s[j][1] = 0.0f; s[j][2] = 0.0f; s[j][3] = 0.0f;
        }
#pragma unroll
        for (int kd = 0; kd < 4; kd++) {
#pragma unroll
            for (int jn = 0; jn < 2; jn++) {
                u32 kh4[4];
                u32 kl4[4];
                const u32 off = (u32)((jn * 16 + browK) * ALD + kd * 16 + bcolK) * 2u;
                ldsm4(kh4, tb + off);
                ldsm4(kl4, tb + AARR + off);
                mma16816(s[jn * 2 + 0], qh[kd], &kh4[0]);
                mma16816(s[jn * 2 + 0], qh[kd], &kl4[0]);
                mma16816(s[jn * 2 + 0], ql[kd], &kh4[0]);
                mma16816(s[jn * 2 + 1], qh[kd], &kh4[2]);
                mma16816(s[jn * 2 + 1], qh[kd], &kl4[2]);
                mma16816(s[jn * 2 + 1], ql[kd], &kh4[2]);
            }
        }

        // causal mask (last two tiles only)
        if (k0 + 32 > q0) {
#pragma unroll
            for (int j = 0; j < 4; j++) {
#pragma unroll
                for (int e = 0; e < 4; e++) {
                    const int kidx = k0 + j * 8 + t * 2 + (e & 1);
                    const int qidx = q0 + wid * 16 + g + (e >> 1) * 8;
                    if (kidx > qidx) s[j][e] = -1e30f;
                }
            }
        }

        // online softmax (base 2), row pair (g, g+8)
        {
            float mx0 = -1e30f;
            float mx1 = -1e30f;
#pragma unroll
            for (int j = 0; j < 4; j++) {
                mx0 = fmaxf(mx0, fmaxf(s[j][0], s[j][1]));
                mx1 = fmaxf(mx1, fmaxf(s[j][2], s[j][3]));
            }
            mx0 = fmaxf(mx0, __shfl_xor_sync(0xffffffffu, mx0, 1));
            mx0 = fmaxf(mx0, __shfl_xor_sync(0xffffffffu, mx0, 2));
            mx1 = fmaxf(mx1, __shfl_xor_sync(0xffffffffu, mx1, 1));
            mx1 = fmaxf(mx1, __shfl_xor_sync(0xffffffffu, mx1, 2));

            const float mn0 = fmaxf(mrow0, mx0);
            const float mn1 = fmaxf(mrow1, mx1);
            const float al0 = exp2f(mrow0 - mn0);
            const float al1 = exp2f(mrow1 - mn1);
            float sum0 = 0.0f;
            float sum1 = 0.0f;
#pragma unroll
            for (int j = 0; j < 4; j++) {
                const float p0 = exp2f(s[j][0] - mn0);
                const float p1 = exp2f(s[j][1] - mn0);
                const float p2 = exp2f(s[j][2] - mn1);
                const float p3 = exp2f(s[j][3] - mn1);
                s[j][0] = p0;
                s[j][1] = p1;
                s[j][2] = p2;
                s[j][3] = p3;
                sum0 += p0 + p1;
                sum1 += p2 + p3;
            }
            sum0 += __shfl_xor_sync(0xffffffffu, sum0, 1);
            sum0 += __shfl_xor_sync(0xffffffffu, sum0, 2);
            sum1 += __shfl_xor_sync(0xffffffffu, sum1, 1);
            sum1 += __shfl_xor_sync(0xffffffffu, sum1, 2);
            lrow0 = lrow0 * al0 + sum0;
            lrow1 = lrow1 * al1 + sum1;
            mrow0 = mn0;
            mrow1 = mn1;
#pragma unroll
            for (int j = 0; j < 8; j++) {
                o[j][0] *= al0;
                o[j][1] *= al0;
                o[j][2] *= al1;
                o[j][3] *= al1;
            }
        }

        // O += P @ V  (P fp16, V hi only), 32 keys
#pragma unroll
        for (int kk = 0; kk < 2; kk++) {
            u32 pa[4];
            pa[0] = packf2(s[2 * kk + 0][0], s[2 * kk + 0][1]);
            pa[1] = packf2(s[2 * kk + 0][2], s[2 * kk + 0][3]);
            pa[2] = packf2(s[2 * kk + 1][0], s[2 * kk + 1][1]);
            pa[3] = packf2(s[2 * kk + 1][2], s[2 * kk + 1][3]);
#pragma unroll
            for (int jd = 0; jd < 4; jd++) {
                u32 vh4[4];
                const u32 off = (u32)((kk * 16 + vrow) * ALD + jd * 16 + vcol) * 2u;
                ldsm4t(vh4, tb + 2 * AARR + off);
                mma16816(o[jd * 2 + 0], pa, &vh4[0]);
                mma16816(o[jd * 2 + 1], pa, &vh4[2]);
            }
        }
        __syncthreads();
    }

    // epilogue: normalize, hi/lo split, store to AO
    const int bb = bh >> 4;
    const int hh = bh & 15;
    const float il0 = 1.0f / lrow0;
    const float il1 = 1.0f / lrow1;
    const int qa = q0 + wid * 16 + g;
    const size_t rowa = ((size_t)bb * S_ + qa) * DM_ + hh * HD_;
    const size_t rowb = ((size_t)bb * S_ + qa + 8) * DM_ + hh * HD_;
#pragma unroll
    for (int j = 0; j < 8; j++) {
        const int dd = j * 8 + t * 2;
        const float v0 = o[j][0] * il0;
        const float v1 = o[j][1] * il0;
        const float v2 = o[j][2] * il1;
        const float v3 = o[j][3] * il1;
        const __half p0 = __float2half_rn(v0);
        const __half p1 = __float2half_rn(v1);
        const __half p2 = __float2half_rn(v2);
        const __half p3 = __float2half_rn(v3);
        const __half e0 = __float2half_rn(v0 - __half2float(p0));
        const __half e1 = __float2half_rn(v1 - __half2float(p1));
        const __half e2 = __float2half_rn(v2 - __half2float(p2));
        const __half e3 = __float2half_rn(v3 - __half2float(p3));
        *(__half2*)&g_AOhi[rowa + dd] = __halves2half2(p0, p1);
        *(__half2*)&g_AOlo[rowa + dd] = __halves2half2(e0, e1);
        *(__half2*)&g_AOhi[rowb + dd] = __halves2half2(p2, p3);
        *(__half2*)&g_AOlo[rowb + dd] = __halves2half2(e2, e3);
    }
}

// ---------------------------------------------------------------------------
extern "C" void kernel_launch(void* const* d_in, const int* in_sizes, int n_in,
                              void* d_out, int out_size)
{
    const float* x  = (const float*)d_in[0];
    const int*   tp = (const int*)d_in[1];
    const float* Wq = (const float*)d_in[2];
    const float* Wk = (const float*)d_in[3];
    const float* Wv = (const float*)d_in[4];
    const float* Wo = (const float*)d_in[5];
    float* out = (float*)d_out;

    static int attr_done = 0;
    if (!attr_done) {
        cudaFuncSetAttribute(hgemm_kernel<0>,
                             cudaFuncAttributeMaxDynamicSharedMemorySize, GSMEM);
        cudaFuncSetAttribute(hgemm_kernel<1>,
                             cudaFuncAttributeMaxDynamicSharedMemorySize, GSMEM);
        attr_done = 1;
    }

    split_x_kernel<<<512, 256>>>(x);
    {
        dim3 grid(128, 4);
        split_w_kernel<<<grid, 256>>>(Wq, Wk, Wv, Wo);
    }
    {
        dim3 grid(DM_ / 128, M_ / 128, 3);
        hgemm_kernel<0><<<grid, 256, GSMEM>>>(tp, nullptr);
    }
    {
        dim3 grid(S_ / 64, B_ * H_);
        attn_kernel<<<grid, 128>>>();
    }
    {
        dim3 grid(DM_ / 128, M_ / 128, 1);
        hgemm_kernel<1><<<grid, 256, GSMEM>>>(nullptr, out);
    }
}

// round 14
// speedup vs baseline: 1.0804x; 1.0088x over previous
#include <cuda_runtime.h>
#include <cuda_fp16.h>
#include <stdint.h>
#include <math.h>
#include <float.h>

typedef unsigned int u32;

#define B_   2
#define S_   2048
#define H_   16
#define HD_  64
#define DM_  1024
#define M_   (B_ * S_)

// ---------------- device scratch (no allocations allowed) ------------------
__device__ __half g_Xhi[(size_t)M_ * DM_];
__device__ __half g_Xlo[(size_t)M_ * DM_];
__device__ __half g_Whi[(size_t)4 * DM_ * DM_];
__device__ __half g_Wlo[(size_t)4 * DM_ * DM_];
__device__ __half g_Qhi[(size_t)M_ * DM_];   // [b,h,s,d], pre-scaled by 0.125*log2(e)
__device__ __half g_Qlo[(size_t)M_ * DM_];
__device__ __half g_Khi[(size_t)M_ * DM_];
__device__ __half g_Klo[(size_t)M_ * DM_];
__device__ __half g_Vhi[(size_t)M_ * DM_];
__device__ __half g_AOhi[(size_t)M_ * DM_];
__device__ __half g_AOlo[(size_t)M_ * DM_];
__device__ float  g_rcos[(size_t)S_ * 32];
__device__ float  g_rsin[(size_t)S_ * 32];

// ---------------- PTX helpers ----------------------------------------------
__device__ __forceinline__ u32 s2u(const void* p)
{
    u32 a;
    asm("{ .reg .u64 t; cvta.to.shared.u64 t, %1; cvt.u32.u64 %0, t; }"
        : "=r"(a) : "l"(p));
    return a;
}

__device__ __forceinline__ void ldsm4(u32* r, u32 addr)
{
    asm volatile("ldmatrix.sync.aligned.m8n8.x4.shared.b16 {%0,%1,%2,%3},[%4];"
                 : "=r"(r[0]), "=r"(r[1]), "=r"(r[2]), "=r"(r[3]) : "r"(addr));
}

__device__ __forceinline__ void ldsm4t(u32* r, u32 addr)
{
    asm volatile("ldmatrix.sync.aligned.m8n8.x4.trans.shared.b16 {%0,%1,%2,%3},[%4];"
                 : "=r"(r[0]), "=r"(r[1]), "=r"(r[2]), "=r"(r[3]) : "r"(addr));
}

__device__ __forceinline__ void mma16816(float* c, const u32* a, const u32* b)
{
    asm volatile("mma.sync.aligned.m16n8k16.row.col.f32.f16.f16.f32 "
                 "{%0,%1,%2,%3},{%4,%5,%6,%7},{%8,%9},{%0,%1,%2,%3};"
                 : "+f"(c[0]), "+f"(c[1]), "+f"(c[2]), "+f"(c[3])
                 : "r"(a[0]), "r"(a[1]), "r"(a[2]), "r"(a[3]),
                   "r"(b[0]), "r"(b[1]));
}

__device__ __forceinline__ u32 packf2(float lo, float hi)
{
    u32 u;
    asm("cvt.rn.f16x2.f32 %0, %1, %2;" : "=r"(u) : "f"(hi), "f"(lo));
    return u;
}

__device__ __forceinline__ void cpa16(u32 saddr, const void* gaddr)
{
    asm volatile("cp.async.cg.shared.global [%0], [%1], 16;"
                 :: "r"(saddr), "l"(gaddr));
}

__device__ __forceinline__ void cp_commit()
{
    asm volatile("cp.async.commit_group;" ::: "memory");
}

__device__ __forceinline__ void cp_wait1()
{
    asm volatile("cp.async.wait_group 1;" ::: "memory");
}

__device__ __forceinline__ void cp_wait0()
{
    asm volatile("cp.async.wait_group 0;" ::: "memory");
}

// ---------------- fp32 -> fp16 hi/lo splitters ------------------------------
__device__ __forceinline__ void split4(const float* src, __half* dh, __half* dl, int i)
{
    float4 v = *(const float4*)&src[i];
    __half h0 = __float2half_rn(v.x);
    __half h1 = __float2half_rn(v.y);
    __half h2 = __float2half_rn(v.z);
    __half h3 = __float2half_rn(v.w);
    __half l0 = __float2half_rn(v.x - __half2float(h0));
    __half l1 = __float2half_rn(v.y - __half2float(h1));
    __half l2 = __float2half_rn(v.z - __half2float(h2));
    __half l3 = __float2half_rn(v.w - __half2float(h3));
    ((__half2*)&dh[i])[0] = __halves2half2(h0, h1);
    ((__half2*)&dh[i])[1] = __halves2half2(h2, h3);
    ((__half2*)&dl[i])[0] = __halves2half2(l0, l1);
    ((__half2*)&dl[i])[1] = __halves2half2(l2, l3);
}

__global__ __launch_bounds__(256) void split_x_kernel(const float* __restrict__ src)
{
    const int n = M_ * DM_;
    for (int i = (blockIdx.x * blockDim.x + threadIdx.x) * 4; i < n;
         i += gridDim.x * blockDim.x * 4) {
        split4(src, g_Xhi, g_Xlo, i);
    }
}

__global__ __launch_bounds__(256) void split_w_kernel(const float* __restrict__ w0,
                                                      const float* __restrict__ w1,
                                                      const float* __restrict__ w2,
                                                      const float* __restrict__ w3)
{
    const int which = blockIdx.y;
    const float* src = (which == 0) ? w0 : ((which == 1) ? w1 : ((which == 2) ? w2 : w3));
    __half* dh = g_Whi + (size_t)which * (DM_ * DM_);
    __half* dl = g_Wlo + (size_t)which * (DM_ * DM_);
    const int n = DM_ * DM_;
    for (int i = (blockIdx.x * blockDim.x + threadIdx.x) * 4; i < n;
         i += gridDim.x * blockDim.x * 4) {
        split4(src, dh, dl, i);
    }
}

// ---------------- RoPE cos/sin table (one-shot) -----------------------------
__global__ __launch_bounds__(256) void rope_table_kernel(const int* __restrict__ tpos)
{
    const int i = blockIdx.x * blockDim.x + threadIdx.x;   // 0..65535
    if (i >= S_ * 32) return;
    const int s  = i >> 5;
    const int d2 = i & 31;
    const float pos = (float)tpos[s];
    const float inv = expf(-(float)(2 * d2) * 0.14391156931f);  // ln(10000)/64
    float sn, cs;
    sincosf(pos * inv, &sn, &cs);
    g_rcos[i] = cs;
    g_rsin[i] = sn;
}

// ---------------- fp16 hi/lo split GEMM, cp.async 2-stage, BK=32 ------------
// Y[m,n] = sum_k A[m,k] * W[n,k]; fp32 acc; combos hh + hl + lh.
// Block 128x128, 8 warps (2m x 4n), warp tile 64x32. Dynamic smem 80 KB.
#define GLD   40
#define GARR  (128 * GLD * 2)          // bytes per array per stage = 10240
#define GOFF_ALO  GARR
#define GOFF_BHI  (2 * GARR)
#define GOFF_BLO  (3 * GARR)
#define GSSB  (4 * GARR)               // stage stride bytes = 40960
#define GSMEM (2 * GSSB)               // 81920

__device__ __forceinline__ void gemm_stage_load(u32 sb, int st, int tid,
                                                int m0, int n0, int k0,
                                                const __half* Ahi, const __half* Alo,
                                                const __half* Bhi, const __half* Blo)
{
#pragma unroll
    for (int u = 0; u < 2; u++) {
        const int id  = tid * 2 + u;      // 0..511
        const int row = id >> 2;          // 0..127
        const int c   = (id & 3) * 8;     // 0,8,16,24
        const u32 so  = sb + (u32)(st * GSSB) + (u32)(row * GLD + c) * 2u;
        cpa16(so,            &Ahi[(size_t)(m0 + row) * DM_ + k0 + c]);
        cpa16(so + GOFF_ALO, &Alo[(size_t)(m0 + row) * DM_ + k0 + c]);
        cpa16(so + GOFF_BHI, &Bhi[(size_t)(n0 + row) * DM_ + k0 + c]);
        cpa16(so + GOFF_BLO, &Blo[(size_t)(n0 + row) * DM_ + k0 + c]);
    }
}

template <int MODE>
__global__ __launch_bounds__(256) void hgemm_kernel(float* __restrict__ outp)
{
    extern __shared__ __half gsm[];

    const int z = (MODE == 0) ? blockIdx.z : 3;
    const __half* Ahi = (MODE == 0) ? g_Xhi : g_AOhi;
    const __half* Alo = (MODE == 0) ? g_Xlo : g_AOlo;
    const __half* Bhi = g_Whi + (size_t)z * DM_ * DM_;
    const __half* Blo = g_Wlo + (size_t)z * DM_ * DM_;

    const int tid  = threadIdx.x;
    const int lane = tid & 31;
    const int wid  = tid >> 5;
    const int wm   = wid >> 2;
    const int wn   = wid & 3;
    const int m0   = blockIdx.y * 128;
    const int n0   = blockIdx.x * 128;

    const u32 sb = s2u(gsm);

    float acc[4][4][4];
#pragma unroll
    for (int i = 0; i < 4; i++) {
#pragma unroll
        for (int j = 0; j < 4; j++) {
            acc[i][j][0] = 0.0f; acc[i][j][1] = 0.0f;
            acc[i][j][2] = 0.0f; acc[i][j][3] = 0.0f;
        }
    }

    const int arow = wm * 64 + (lane & 15);
    const int acol = (lane >> 4) << 3;
    const int brow = wn * 32 + (lane & 7) + ((lane & 16) ? 8 : 0);
    const int bcol = (lane & 8) ? 8 : 0;

    gemm_stage_load(sb, 0, tid, m0, n0, 0, Ahi, Alo, Bhi, Blo);
    cp_commit();

    for (int it = 0; it < 32; it++) {
        if (it < 31) {
            gemm_stage_load(sb, (it + 1) & 1, tid, m0, n0, (it + 1) * 32,
                            Ahi, Alo, Bhi, Blo);
            cp_commit();
            cp_wait1();
        } else {
            cp_wait0();
        }
        __syncthreads();

        const u32 tb = sb + (u32)((it & 1) * GSSB);

#pragma unroll
        for (int ks = 0; ks < 32; ks += 16) {
            u32 ah[4][4];
            u32 al[4][4];
            u32 bh2[2][4];
            u32 bl2[2][4];
#pragma unroll
            for (int i = 0; i < 4; i++) {
                const u32 off = (u32)((arow + i * 16) * GLD + ks + acol) * 2u;
                ldsm4(ah[i], tb + off);
                ldsm4(al[i], tb + GOFF_ALO + off);
            }
#pragma unroll
            for (int jn = 0; jn < 2; jn++) {
                const u32 off = (u32)((brow + jn * 16) * GLD + ks + bcol) * 2u;
                ldsm4(bh2[jn], tb + GOFF_BHI + off);
                ldsm4(bl2[jn], tb + GOFF_BLO + off);
            }
#pragma unroll
            for (int i = 0; i < 4; i++) {
#pragma unroll
                for (int j = 0; j < 4; j++) {
                    const u32* Bh = &bh2[j >> 1][(j & 1) * 2];
                    const u32* Bl = &bl2[j >> 1][(j & 1) * 2];
                    mma16816(acc[i][j], ah[i], Bh);
                    mma16816(acc[i][j], ah[i], Bl);
                    mma16816(acc[i][j], al[i], Bh);
                }
            }
        }
        __syncthreads();   // all reads of this stage done before it is reloaded
    }

    const int g = lane >> 2;
    const int t = lane & 3;

    if (MODE == 1) {
#pragma unroll
        for (int i = 0; i < 4; i++) {
            const int m = m0 + wm * 64 + i * 16 + g;
#pragma unroll
            for (int j = 0; j < 4; j++) {
                const int n = n0 + wn * 32 + j * 8 + t * 2;
                *(float2*)&outp[(size_t)m * DM_ + n] = make_float2(acc[i][j][0], acc[i][j][1]);
                *(float2*)&outp[(size_t)(m + 8) * DM_ + n] = make_float2(acc[i][j][2], acc[i][j][3]);
            }
        }
        return;
    }

    // MODE 0 epilogue: RoPE via table (z<2), scale (z==0 folds 0.125*log2e),
    // hi/lo split. V (z==2): hi only.
    __half* Dhi = (z == 0) ? g_Qhi : ((z == 1) ? g_Khi : g_Vhi);
    __half* Dlo = (z == 0) ? g_Qlo : g_Klo;   // unused for z==2
    const float qscale = 0.18033688011f;      // 0.125 * log2(e)
#pragma unroll
    for (int i = 0; i < 4; i++) {
#pragma unroll
        for (int rr = 0; rr < 2; rr++) {
            const int m = m0 + wm * 64 + i * 16 + g + rr * 8;
            const int bb = m >> 11;
            const int ss = m & (S_ - 1);
#pragma unroll
            for (int j = 0; j < 4; j++) {
                const int n = n0 + wn * 32 + j * 8 + t * 2;
                const int hh = n >> 6;
                const int dd = n & 63;
                float v0 = acc[i][j][rr * 2 + 0];
                float v1 = acc[i][j][rr * 2 + 1];
                if (z < 2) {
                    const int ridx = ss * 32 + (dd >> 1);
                    const float cs = g_rcos[ridx];
                    const float sn = g_rsin[ridx];
                    const float r1 = v0 * cs - v1 * sn;
                    const float r2 = v0 * sn + v1 * cs;
                    v0 = r1;
                    v1 = r2;
                }
                if (z == 0) {
                    v0 *= qscale;
                    v1 *= qscale;
                }
                const __half p0 = __float2half_rn(v0);
                const __half p1 = __float2half_rn(v1);
                const size_t ofs = ((size_t)(bb * H_ + hh) * S_ + ss) * HD_ + dd;
                *(__half2*)&Dhi[ofs] = __halves2half2(p0, p1);
                if (z < 2) {
                    const __half e0 = __float2half_rn(v0 - __half2float(p0));
                    const __half e1 = __float2half_rn(v1 - __half2float(p1));
                    *(__half2*)&Dlo[ofs] = __halves2half2(e0, e1);
                }
            }
        }
    }
}

// ---------------- mma flash attention (causal), cp.async double-buffered ----
// 32-key tiles; stage = [Kh][Kl][Vh] (27.6 KB static total). Base-2 softmax.
#define ALD  72
#define AARR (32 * ALD * 2)        // 4608 bytes
#define ASTG (3 * AARR)            // 13824 bytes per stage

__device__ __forceinline__ void attn_stage_load(u32 sb, int st, int tid,
                                                size_t gbase, int k0)
{
#pragma unroll
    for (int u = 0; u < 2; u++) {
        const int id  = tid * 2 + u;      // 0..255
        const int row = id >> 3;          // 0..31
        const int c   = (id & 7) * 8;     // 0..56
        const size_t go = gbase + (size_t)(k0 + row) * HD_ + c;
        const u32 so = sb + (u32)(st * ASTG) + (u32)(row * ALD + c) * 2u;
        cpa16(so,            &g_Khi[go]);
        cpa16(so + AARR,     &g_Klo[go]);
        cpa16(so + 2 * AARR, &g_Vhi[go]);
    }
}

__global__ __launch_bounds__(128) void attn_kernel()
{
    __shared__ __half smem[2 * ASTG / 2];   // 27648 bytes

    const int tid  = threadIdx.x;
    const int lane = tid & 31;
    const int wid  = tid >> 5;
    const int q0   = (gridDim.x - 1 - blockIdx.x) * 64;   // long blocks first
    const int bh   = blockIdx.y;
    const size_t gbase = (size_t)bh * S_ * HD_;

    const u32 sb = s2u(smem);

    // ---- stage Q tile (hi at 0, lo at 64*ALD) and pull fragments ----
    for (int u = tid; u < 512; u += 128) {
        const int row = u >> 3;
        const int c   = (u & 7) * 8;
        *(int4*)&smem[row * ALD + c] =
            *(const int4*)&g_Qhi[gbase + (size_t)(q0 + row) * HD_ + c];
        *(int4*)&smem[64 * ALD + row * ALD + c] =
            *(const int4*)&g_Qlo[gbase + (size_t)(q0 + row) * HD_ + c];
    }
    __syncthreads();

    u32 qh[4][4];
    u32 ql[4][4];
    {
        const int row = wid * 16 + (lane & 15);
        const int col = (lane >> 4) << 3;
        const u32 qlo_off = (u32)(64 * ALD) * 2u;
#pragma unroll
        for (int kd = 0; kd < 4; kd++) {
            const u32 off = (u32)(row * ALD + kd * 16 + col) * 2u;
            ldsm4(qh[kd], sb + off);
            ldsm4(ql[kd], sb + qlo_off + off);
        }
    }
    __syncthreads();

    float o[8][4];
#pragma unroll
    for (int j = 0; j < 8; j++) {
        o[j][0] = 0.0f; o[j][1] = 0.0f; o[j][2] = 0.0f; o[j][3] = 0.0f;
    }
    float mrow0 = -1e30f;
    float mrow1 = -1e30f;
    float lrow0 = 0.0f;
    float lrow1 = 0.0f;

    const int g = lane >> 2;
    const int t = lane & 3;
    const int browK = (lane & 7) + ((lane & 16) ? 8 : 0);
    const int bcolK = (lane & 8) ? 8 : 0;
    const int vrow  = lane & 15;
    const int vcol  = (lane >> 4) << 3;

    const int ntiles = q0 / 32 + 2;     // keys 0 .. q0+63

    attn_stage_load(sb, 0, tid, gbase, 0);
    cp_commit();

    for (int it = 0; it < ntiles; it++) {
        const int k0 = it * 32;
        if (it + 1 < ntiles) {
            attn_stage_load(sb, (it + 1) & 1, tid, gbase, (it + 1) * 32);
            cp_commit();
            cp_wait1();
        } else {
            cp_wait0();
        }
        __syncthreads();

        const u32 tb = sb + (u32)((it & 1) * ASTG);

        // S = Q K^T over 32 keys (Q pre-scaled by 0.125*log2e -> base-2 space)
        float s[4][4];
#pragma unroll
        for (int j = 0; j < 4; j++) {
            s[j][0] = 0.0f; s[j][1] = 0.0f; s[j][2] = 0.0f; s[j][3] = 0.0f;
        }
#pragma unroll
        for (int kd = 0; kd < 4; kd++) {
#pragma unroll
            for (int jn = 0; jn < 2; jn++) {
                u32 kh4[4];
                u32 kl4[4];
                const u32 off = (u32)((jn * 16 + browK) * ALD + kd * 16 + bcolK) * 2u;
                ldsm4(kh4, tb + off);
                ldsm4(kl4, tb + AARR + off);
                mma16816(s[jn * 2 + 0], qh[kd], &kh4[0]);
                mma16816(s[jn * 2 + 0], qh[kd], &kl4[0]);
                mma16816(s[jn * 2 + 0], ql[kd], &kh4[0]);
                mma16816(s[jn * 2 + 1], qh[kd], &kh4[2]);
                mma16816(s[jn * 2 + 1], qh[kd], &kl4[2]);
                mma16816(s[jn * 2 + 1], ql[kd], &kh4[2]);
            }
        }

        // causal mask (last two tiles only)
        if (k0 + 32 > q0) {
#pragma unroll
            for (int j = 0; j < 4; j++) {
#pragma unroll
                for (int e = 0; e < 4; e++) {
                    const int kidx = k0 + j * 8 + t * 2 + (e & 1);
                    const int qidx = q0 + wid * 16 + g + (e >> 1) * 8;
                    if (kidx > qidx) s[j][e] = -1e30f;
                }
            }
        }

        // online softmax (base 2), row pair (g, g+8)
        {
            float mx0 = -1e30f;
            float mx1 = -1e30f;
#pragma unroll
            for (int j = 0; j < 4; j++) {
                mx0 = fmaxf(mx0, fmaxf(s[j][0], s[j][1]));
                mx1 = fmaxf(mx1, fmaxf(s[j][2], s[j][3]));
            }
            mx0 = fmaxf(mx0, __shfl_xor_sync(0xffffffffu, mx0, 1));
            mx0 = fmaxf(mx0, __shfl_xor_sync(0xffffffffu, mx0, 2));
            mx1 = fmaxf(mx1, __shfl_xor_sync(0xffffffffu, mx1, 1));
            mx1 = fmaxf(mx1, __shfl_xor_sync(0xffffffffu, mx1, 2));

            const float mn0 = fmaxf(mrow0, mx0);
            const float mn1 = fmaxf(mrow1, mx1);
            const float al0 = exp2f(mrow0 - mn0);
            const float al1 = exp2f(mrow1 - mn1);
            float sum0 = 0.0f;
            float sum1 = 0.0f;
#pragma unroll
            for (int j = 0; j < 4; j++) {
                const float p0 = exp2f(s[j][0] - mn0);
                const float p1 = exp2f(s[j][1] - mn0);
                const float p2 = exp2f(s[j][2] - mn1);
                const float p3 = exp2f(s[j][3] - mn1);
                s[j][0] = p0;
                s[j][1] = p1;
                s[j][2] = p2;
                s[j][3] = p3;
                sum0 += p0 + p1;
                sum1 += p2 + p3;
            }
            sum0 += __shfl_xor_sync(0xffffffffu, sum0, 1);
            sum0 += __shfl_xor_sync(0xffffffffu, sum0, 2);
            sum1 += __shfl_xor_sync(0xffffffffu, sum1, 1);
            sum1 += __shfl_xor_sync(0xffffffffu, sum1, 2);
            lrow0 = lrow0 * al0 + sum0;
            lrow1 = lrow1 * al1 + sum1;
            mrow0 = mn0;
            mrow1 = mn1;
#pragma unroll
            for (int j = 0; j < 8; j++) {
                o[j][0] *= al0;
                o[j][1] *= al0;
                o[j][2] *= al1;
                o[j][3] *= al1;
            }
        }

        // O += P @ V  (P fp16, V hi only), 32 keys
#pragma unroll
        for (int kk = 0; kk < 2; kk++) {
            u32 pa[4];
            pa[0] = packf2(s[2 * kk + 0][0], s[2 * kk + 0][1]);
            pa[1] = packf2(s[2 * kk + 0][2], s[2 * kk + 0][3]);
            pa[2] = packf2(s[2 * kk + 1][0], s[2 * kk + 1][1]);
            pa[3] = packf2(s[2 * kk + 1][2], s[2 * kk + 1][3]);
#pragma unroll
            for (int jd = 0; jd < 4; jd++) {
                u32 vh4[4];
                const u32 off = (u32)((kk * 16 + vrow) * ALD + jd * 16 + vcol) * 2u;
                ldsm4t(vh4, tb + 2 * AARR + off);
                mma16816(o[jd * 2 + 0], pa, &vh4[0]);
                mma16816(o[jd * 2 + 1], pa, &vh4[2]);
            }
        }
        __syncthreads();
    }

    // epilogue: normalize, hi/lo split, store to AO
    const int bb = bh >> 4;
    const int hh = bh & 15;
    const float il0 = 1.0f / lrow0;
    const float il1 = 1.0f / lrow1;
    const int qa = q0 + wid * 16 + g;
    const size_t rowa = ((size_t)bb * S_ + qa) * DM_ + hh * HD_;
    const size_t rowb = ((size_t)bb * S_ + qa + 8) * DM_ + hh * HD_;
#pragma unroll
    for (int j = 0; j < 8; j++) {
        const int dd = j * 8 + t * 2;
        const float v0 = o[j][0] * il0;
        const float v1 = o[j][1] * il0;
        const float v2 = o[j][2] * il1;
        const float v3 = o[j][3] * il1;
        const __half p0 = __float2half_rn(v0);
        const __half p1 = __float2half_rn(v1);
        const __half p2 = __float2half_rn(v2);
        const __half p3 = __float2half_rn(v3);
        const __half e0 = __float2half_rn(v0 - __half2float(p0));
        const __half e1 = __float2half_rn(v1 - __half2float(p1));
        const __half e2 = __float2half_rn(v2 - __half2float(p2));
        const __half e3 = __float2half_rn(v3 - __half2float(p3));
        *(__half2*)&g_AOhi[rowa + dd] = __halves2half2(p0, p1);
        *(__half2*)&g_AOlo[rowa + dd] = __halves2half2(e0, e1);
        *(__half2*)&g_AOhi[rowb + dd] = __halves2half2(p2, p3);
        *(__half2*)&g_AOlo[rowb + dd] = __halves2half2(e2, e3);
    }
}

// ---------------------------------------------------------------------------
extern "C" void kernel_launch(void* const* d_in, const int* in_sizes, int n_in,
                              void* d_out, int out_size)
{
    const float* x  = (const float*)d_in[0];
    const int*   tp = (const int*)d_in[1];
    const float* Wq = (const float*)d_in[2];
    const float* Wk = (const float*)d_in[3];
    const float* Wv = (const float*)d_in[4];
    const float* Wo = (const float*)d_in[5];
    float* out = (float*)d_out;

    static int attr_done = 0;
    if (!attr_done) {
        cudaFuncSetAttribute(hgemm_kernel<0>,
                             cudaFuncAttributeMaxDynamicSharedMemorySize, GSMEM);
        cudaFuncSetAttribute(hgemm_kernel<1>,
                             cudaFuncAttributeMaxDynamicSharedMemorySize, GSMEM);
        attr_done = 1;
    }

    rope_table_kernel<<<256, 256>>>(tp);
    split_x_kernel<<<512, 256>>>(x);
    {
        dim3 grid(128, 4);
        split_w_kernel<<<grid, 256>>>(Wq, Wk, Wv, Wo);
    }
    {
        dim3 grid(DM_ / 128, M_ / 128, 3);
        hgemm_kernel<0><<<grid, 256, GSMEM>>>(nullptr);
    }
    {
        dim3 grid(S_ / 64, B_ * H_);
        attn_kernel<<<grid, 128>>>();
    }
    {
        dim3 grid(DM_ / 128, M_ / 128, 1);
        hgemm_kernel<1><<<grid, 256, GSMEM>>>(out);
    }
}

// round 15
// speedup vs baseline: 1.2929x; 1.1966x over previous
#include <cuda_runtime.h>
#include <cuda_fp16.h>
#include <stdint.h>
#include <math.h>
#include <float.h>

typedef unsigned int u32;

#define B_   2
#define S_   2048
#define H_   16
#define HD_  64
#define DM_  1024
#define M_   (B_ * S_)

// ---------------- device scratch (no allocations allowed) ------------------
__device__ __half g_Xhi[(size_t)M_ * DM_];
__device__ __half g_Whi[(size_t)4 * DM_ * DM_];
__device__ __half g_Wlo[(size_t)4 * DM_ * DM_];
__device__ __half g_Qhi[(size_t)M_ * DM_];   // [b,h,s,d], pre-scaled by 0.125*log2(e)
__device__ __half g_Qlo[(size_t)M_ * DM_];
__device__ __half g_Khi[(size_t)M_ * DM_];
__device__ __half g_Klo[(size_t)M_ * DM_];
__device__ __half g_Vhi[(size_t)M_ * DM_];
__device__ __half g_AOhi[(size_t)M_ * DM_];
__device__ float  g_rcos[(size_t)S_ * 32];
__device__ float  g_rsin[(size_t)S_ * 32];

// ---------------- PTX helpers ----------------------------------------------
__device__ __forceinline__ u32 s2u(const void* p)
{
    u32 a;
    asm("{ .reg .u64 t; cvta.to.shared.u64 t, %1; cvt.u32.u64 %0, t; }"
        : "=r"(a) : "l"(p));
    return a;
}

__device__ __forceinline__ void ldsm4(u32* r, u32 addr)
{
    asm volatile("ldmatrix.sync.aligned.m8n8.x4.shared.b16 {%0,%1,%2,%3},[%4];"
                 : "=r"(r[0]), "=r"(r[1]), "=r"(r[2]), "=r"(r[3]) : "r"(addr));
}

__device__ __forceinline__ void ldsm4t(u32* r, u32 addr)
{
    asm volatile("ldmatrix.sync.aligned.m8n8.x4.trans.shared.b16 {%0,%1,%2,%3},[%4];"
                 : "=r"(r[0]), "=r"(r[1]), "=r"(r[2]), "=r"(r[3]) : "r"(addr));
}

__device__ __forceinline__ void mma16816(float* c, const u32* a, const u32* b)
{
    asm volatile("mma.sync.aligned.m16n8k16.row.col.f32.f16.f16.f32 "
                 "{%0,%1,%2,%3},{%4,%5,%6,%7},{%8,%9},{%0,%1,%2,%3};"
                 : "+f"(c[0]), "+f"(c[1]), "+f"(c[2]), "+f"(c[3])
                 : "r"(a[0]), "r"(a[1]), "r"(a[2]), "r"(a[3]),
                   "r"(b[0]), "r"(b[1]));
}

__device__ __forceinline__ u32 packf2(float lo, float hi)
{
    u32 u;
    asm("cvt.rn.f16x2.f32 %0, %1, %2;" : "=r"(u) : "f"(hi), "f"(lo));
    return u;
}

__device__ __forceinline__ void cpa16(u32 saddr, const void* gaddr)
{
    asm volatile("cp.async.cg.shared.global [%0], [%1], 16;"
                 :: "r"(saddr), "l"(gaddr));
}

__device__ __forceinline__ void cp_commit()
{
    asm volatile("cp.async.commit_group;" ::: "memory");
}

__device__ __forceinline__ void cp_wait1()
{
    asm volatile("cp.async.wait_group 1;" ::: "memory");
}

__device__ __forceinline__ void cp_wait0()
{
    asm volatile("cp.async.wait_group 0;" ::: "memory");
}

__device__ __forceinline__ u32 swz64(u32 b)
{
    return b ^ ((b >> 3) & 0x30u);
}

// ---------------- fp32 -> fp16 splitters ------------------------------------
__global__ __launch_bounds__(256) void split_x_kernel(const float* __restrict__ src)
{
    const int n = M_ * DM_;
    for (int i = (blockIdx.x * blockDim.x + threadIdx.x) * 4; i < n;
         i += gridDim.x * blockDim.x * 4) {
        float4 v = *(const float4*)&src[i];
        ((__half2*)&g_Xhi[i])[0] = __halves2half2(__float2half_rn(v.x), __float2half_rn(v.y));
        ((__half2*)&g_Xhi[i])[1] = __halves2half2(__float2half_rn(v.z), __float2half_rn(v.w));
    }
}

__global__ __launch_bounds__(256) void split_w_kernel(const float* __restrict__ w0,
                                                      const float* __restrict__ w1,
                                                      const float* __restrict__ w2,
                                                      const float* __restrict__ w3)
{
    const int which = blockIdx.y;
    const float* src = (which == 0) ? w0 : ((which == 1) ? w1 : ((which == 2) ? w2 : w3));
    __half* dh = g_Whi + (size_t)which * (DM_ * DM_);
    __half* dl = g_Wlo + (size_t)which * (DM_ * DM_);
    const int n = DM_ * DM_;
    for (int i = (blockIdx.x * blockDim.x + threadIdx.x) * 4; i < n;
         i += gridDim.x * blockDim.x * 4) {
        float4 v = *(const float4*)&src[i];
        __half h0 = __float2half_rn(v.x);
        __half h1 = __float2half_rn(v.y);
        __half h2 = __float2half_rn(v.z);
        __half h3 = __float2half_rn(v.w);
        __half l0 = __float2half_rn(v.x - __half2float(h0));
        __half l1 = __float2half_rn(v.y - __half2float(h1));
        __half l2 = __float2half_rn(v.z - __half2float(h2));
        __half l3 = __float2half_rn(v.w - __half2float(h3));
        ((__half2*)&dh[i])[0] = __halves2half2(h0, h1);
        ((__half2*)&dh[i])[1] = __halves2half2(h2, h3);
        ((__half2*)&dl[i])[0] = __halves2half2(l0, l1);
        ((__half2*)&dl[i])[1] = __halves2half2(l2, l3);
    }
}

// ---------------- RoPE cos/sin table (one-shot) -----------------------------
__global__ __launch_bounds__(256) void rope_table_kernel(const int* __restrict__ tpos)
{
    const int i = blockIdx.x * blockDim.x + threadIdx.x;   // 0..65535
    if (i >= S_ * 32) return;
    const int s  = i >> 5;
    const int d2 = i & 31;
    const float pos = (float)tpos[s];
    const float inv = expf(-(float)(2 * d2) * 0.14391156931f);  // ln(10000)/64
    float sn, cs;
    sincosf(pos * inv, &sn, &cs);
    g_rcos[i] = cs;
    g_rsin[i] = sn;
}

// ---------------- fp16 GEMM: A_hi x (W_hi + W_lo) ---------------------------
// Y[m,n] = sum_k A[m,k] * W[n,k]; fp32 acc; combos hh + hl.
// Block 128x128, 8 warps (2m x 4n), warp tile 64x32.
// SW64-swizzled smem (64B rows), 3 stages, ONE barrier per stage.
#define GARR  8192                     // bytes per array per stage (128 x 64B)
#define GOFF_BHI  GARR
#define GOFF_BLO  (2 * GARR)
#define GSSB  (3 * GARR)               // stage stride = 24576
#define GSMEM (3 * GSSB)               // 73728

__device__ __forceinline__ void gemm_stage_load(u32 sb, int st, int tid,
                                                int m0, int n0, int k0,
                                                const __half* A,
                                                const __half* Bh, const __half* Bl)
{
#pragma unroll
    for (int u = 0; u < 2; u++) {
        const int id  = tid * 2 + u;      // 0..511
        const int row = id >> 2;          // 0..127
        const int c16 = id & 3;           // 16B chunk
        const u32 so  = sb + (u32)(st * GSSB) + swz64((u32)(row * 64 + c16 * 16));
        const size_t ga = (size_t)(m0 + row) * DM_ + k0 + c16 * 8;
        const size_t gb = (size_t)(n0 + row) * DM_ + k0 + c16 * 8;
        cpa16(so,            &A[ga]);
        cpa16(so + GOFF_BHI, &Bh[gb]);
        cpa16(so + GOFF_BLO, &Bl[gb]);
    }
}

template <int MODE>
__global__ __launch_bounds__(256) void hgemm_kernel(float* __restrict__ outp)
{
    extern __shared__ __half gsm[];

    const int z = (MODE == 0) ? blockIdx.z : 3;
    const __half* A  = (MODE == 0) ? g_Xhi : g_AOhi;
    const __half* Bh = g_Whi + (size_t)z * DM_ * DM_;
    const __half* Bl = g_Wlo + (size_t)z * DM_ * DM_;

    const int tid  = threadIdx.x;
    const int lane = tid & 31;
    const int wid  = tid >> 5;
    const int wm   = wid >> 2;
    const int wn   = wid & 3;
    const int m0   = blockIdx.y * 128;
    const int n0   = blockIdx.x * 128;

    const u32 sb = s2u(gsm);

    float acc[4][4][4];
#pragma unroll
    for (int i = 0; i < 4; i++) {
#pragma unroll
        for (int j = 0; j < 4; j++) {
            acc[i][j][0] = 0.0f; acc[i][j][1] = 0.0f;
            acc[i][j][2] = 0.0f; acc[i][j][3] = 0.0f;
        }
    }

    const int arow = wm * 64 + (lane & 15);
    const int acol = (lane >> 4) << 3;
    const int brow = wn * 32 + (lane & 7) + ((lane & 16) ? 8 : 0);
    const int bcol = (lane & 8) ? 8 : 0;

    gemm_stage_load(sb, 0, tid, m0, n0, 0, A, Bh, Bl);
    cp_commit();
    gemm_stage_load(sb, 1, tid, m0, n0, 32, A, Bh, Bl);
    cp_commit();

    for (int it = 0; it < 32; it++) {
        if (it < 31) {
            cp_wait1();
        } else {
            cp_wait0();
        }
        __syncthreads();      // stage it visible; compute of it-1 done by all

        if (it < 30) {
            gemm_stage_load(sb, (it + 2) % 3, tid, m0, n0, (it + 2) * 32,
                            A, Bh, Bl);
            cp_commit();
        }

        const u32 tb = sb + (u32)((it % 3) * GSSB);

#pragma unroll
        for (int ks = 0; ks < 32; ks += 16) {
            u32 ah[4][4];
            u32 bh2[2][4];
            u32 bl2[2][4];
#pragma unroll
            for (int i = 0; i < 4; i++) {
                const u32 off = swz64((u32)((arow + i * 16) * 64 + (ks + acol) * 2));
                ldsm4(ah[i], tb + off);
            }
#pragma unroll
            for (int jn = 0; jn < 2; jn++) {
                const u32 off = swz64((u32)((brow + jn * 16) * 64 + (ks + bcol) * 2));
                ldsm4(bh2[jn], tb + GOFF_BHI + off);
                ldsm4(bl2[jn], tb + GOFF_BLO + off);
            }
#pragma unroll
            for (int i = 0; i < 4; i++) {
#pragma unroll
                for (int j = 0; j < 4; j++) {
                    const u32* Bhf = &bh2[j >> 1][(j & 1) * 2];
                    const u32* Blf = &bl2[j >> 1][(j & 1) * 2];
                    mma16816(acc[i][j], ah[i], Bhf);
                    mma16816(acc[i][j], ah[i], Blf);
                }
            }
        }
    }

    const int g = lane >> 2;
    const int t = lane & 3;

    if (MODE == 1) {
#pragma unroll
        for (int i = 0; i < 4; i++) {
            const int m = m0 + wm * 64 + i * 16 + g;
#pragma unroll
            for (int j = 0; j < 4; j++) {
                const int n = n0 + wn * 32 + j * 8 + t * 2;
                *(float2*)&outp[(size_t)m * DM_ + n] = make_float2(acc[i][j][0], acc[i][j][1]);
                *(float2*)&outp[(size_t)(m + 8) * DM_ + n] = make_float2(acc[i][j][2], acc[i][j][3]);
            }
        }
        return;
    }

    // MODE 0 epilogue: RoPE via table (z<2), scale (z==0), hi/lo split (Q,K),
    // V (z==2) hi only.
    __half* Dhi = (z == 0) ? g_Qhi : ((z == 1) ? g_Khi : g_Vhi);
    __half* Dlo = (z == 0) ? g_Qlo : g_Klo;   // unused for z==2
    const float qscale = 0.18033688011f;      // 0.125 * log2(e)
#pragma unroll
    for (int i = 0; i < 4; i++) {
#pragma unroll
        for (int rr = 0; rr < 2; rr++) {
            const int m = m0 + wm * 64 + i * 16 + g + rr * 8;
            const int bb = m >> 11;
            const int ss = m & (S_ - 1);
#pragma unroll
            for (int j = 0; j < 4; j++) {
                const int n = n0 + wn * 32 + j * 8 + t * 2;
                const int hh = n >> 6;
                const int dd = n & 63;
                float v0 = acc[i][j][rr * 2 + 0];
                float v1 = acc[i][j][rr * 2 + 1];
                if (z < 2) {
                    const int ridx = ss * 32 + (dd >> 1);
                    const float cs = g_rcos[ridx];
                    const float sn = g_rsin[ridx];
                    const float r1 = v0 * cs - v1 * sn;
                    const float r2 = v0 * sn + v1 * cs;
                    v0 = r1;
                    v1 = r2;
                }
                if (z == 0) {
                    v0 *= qscale;
                    v1 *= qscale;
                }
                const __half p0 = __float2half_rn(v0);
                const __half p1 = __float2half_rn(v1);
                const size_t ofs = ((size_t)(bb * H_ + hh) * S_ + ss) * HD_ + dd;
                *(__half2*)&Dhi[ofs] = __halves2half2(p0, p1);
                if (z < 2) {
                    const __half e0 = __float2half_rn(v0 - __half2float(p0));
                    const __half e1 = __float2half_rn(v1 - __half2float(p1));
                    *(__half2*)&Dlo[ofs] = __halves2half2(e0, e1);
                }
            }
        }
    }
}

// ---------------- mma flash attention (causal), 3-stage single-barrier ------
// 32-key tiles; stage = [Kh][Kl][Vh] 13.8 KB; 3 stages (41.5 KB static).
#define ALD  72
#define AARR (32 * ALD * 2)        // 4608 bytes
#define ASTG (3 * AARR)            // 13824 bytes per stage

__device__ __forceinline__ void attn_stage_load(u32 sb, int st, int tid,
                                                size_t gbase, int k0)
{
#pragma unroll
    for (int u = 0; u < 2; u++) {
        const int id  = tid * 2 + u;      // 0..255
        const int row = id >> 3;          // 0..31
        const int c   = (id & 7) * 8;     // 0..56
        const size_t go = gbase + (size_t)(k0 + row) * HD_ + c;
        const u32 so = sb + (u32)(st * ASTG) + (u32)(row * ALD + c) * 2u;
        cpa16(so,            &g_Khi[go]);
        cpa16(so + AARR,     &g_Klo[go]);
        cpa16(so + 2 * AARR, &g_Vhi[go]);
    }
}

__global__ __launch_bounds__(128) void attn_kernel()
{
    __shared__ __half smem[3 * ASTG / 2];   // 41472 bytes

    const int tid  = threadIdx.x;
    const int lane = tid & 31;
    const int wid  = tid >> 5;
    const int q0   = (gridDim.x - 1 - blockIdx.x) * 64;   // long blocks first
    const int bh   = blockIdx.y;
    const size_t gbase = (size_t)bh * S_ * HD_;

    const u32 sb = s2u(smem);

    // ---- stage Q tile (hi at 0, lo at 64*ALD) and pull fragments ----
    for (int u = tid; u < 512; u += 128) {
        const int row = u >> 3;
        const int c   = (u & 7) * 8;
        *(int4*)&smem[row * ALD + c] =
            *(const int4*)&g_Qhi[gbase + (size_t)(q0 + row) * HD_ + c];
        *(int4*)&smem[64 * ALD + row * ALD + c] =
            *(const int4*)&g_Qlo[gbase + (size_t)(q0 + row) * HD_ + c];
    }
    __syncthreads();

    u32 qh[4][4];
    u32 ql[4][4];
    {
        const int row = wid * 16 + (lane & 15);
        const int col = (lane >> 4) << 3;
        const u32 qlo_off = (u32)(64 * ALD) * 2u;
#pragma unroll
        for (int kd = 0; kd < 4; kd++) {
            const u32 off = (u32)(row * ALD + kd * 16 + col) * 2u;
            ldsm4(qh[kd], sb + off);
            ldsm4(ql[kd], sb + qlo_off + off);
        }
    }
    __syncthreads();

    float o[8][4];
#pragma unroll
    for (int j = 0; j < 8; j++) {
        o[j][0] = 0.0f; o[j][1] = 0.0f; o[j][2] = 0.0f; o[j][3] = 0.0f;
    }
    float mrow0 = -1e30f;
    float mrow1 = -1e30f;
    float lrow0 = 0.0f;
    float lrow1 = 0.0f;

    const int g = lane >> 2;
    const int t = lane & 3;
    const int browK = (lane & 7) + ((lane & 16) ? 8 : 0);
    const int bcolK = (lane & 8) ? 8 : 0;
    const int vrow  = lane & 15;
    const int vcol  = (lane >> 4) << 3;

    const int ntiles = q0 / 32 + 2;     // keys 0 .. q0+63 (ntiles >= 2)

    attn_stage_load(sb, 0, tid, gbase, 0);
    cp_commit();
    attn_stage_load(sb, 1, tid, gbase, 32);
    cp_commit();

    for (int it = 0; it < ntiles; it++) {
        const int k0 = it * 32;
        if (it < ntiles - 1) {
            cp_wait1();
        } else {
            cp_wait0();
        }
        __syncthreads();      // stage it visible; compute of it-1 done by all

        if (it + 2 < ntiles) {
            attn_stage_load(sb, (it + 2) % 3, tid, gbase, (it + 2) * 32);
            cp_commit();
        }

        const u32 tb = sb + (u32)((it % 3) * ASTG);

        // S = Q K^T over 32 keys (Q pre-scaled by 0.125*log2e -> base-2 space)
        float s[4][4];
#pragma unroll
        for (int j = 0; j < 4; j++) {
            s[j][0] = 0.0f; s[j][1] = 0.0f; s[j][2] = 0.0f; s[j][3] = 0.0f;
        }
#pragma unroll
        for (int kd = 0; kd < 4; kd++) {
#pragma unroll
            for (int jn = 0; jn < 2; jn++) {
                u32 kh4[4];
                u32 kl4[4];
                const u32 off = (u32)((jn * 16 + browK) * ALD + kd * 16 + bcolK) * 2u;
                ldsm4(kh4, tb + off);
                ldsm4(kl4, tb + AARR + off);
                mma16816(s[jn * 2 + 0], qh[kd], &kh4[0]);
                mma16816(s[jn * 2 + 0], qh[kd], &kl4[0]);
                mma16816(s[jn * 2 + 0], ql[kd], &kh4[0]);
                mma16816(s[jn * 2 + 1], qh[kd], &kh4[2]);
                mma16816(s[jn * 2 + 1], qh[kd], &kl4[2]);
                mma16816(s[jn * 2 + 1], ql[kd], &kh4[2]);
            }
        }

        // causal mask (last two tiles only)
        if (k0 + 32 > q0) {
#pragma unroll
            for (int j = 0; j < 4; j++) {
#pragma unroll
                for (int e = 0; e < 4; e++) {
                    const int kidx = k0 + j * 8 + t * 2 + (e & 1);
                    const int qidx = q0 + wid * 16 + g + (e >> 1) * 8;
                    if (kidx > qidx) s[j][e] = -1e30f;
                }
            }
        }

        // online softmax (base 2), row pair (g, g+8)
        {
            float mx0 = -1e30f;
            float mx1 = -1e30f;
#pragma unroll
            for (int j = 0; j < 4; j++) {
                mx0 = fmaxf(mx0, fmaxf(s[j][0], s[j][1]));
                mx1 = fmaxf(mx1, fmaxf(s[j][2], s[j][3]));
            }
            mx0 = fmaxf(mx0, __shfl_xor_sync(0xffffffffu, mx0, 1));
            mx0 = fmaxf(mx0, __shfl_xor_sync(0xffffffffu, mx0, 2));
            mx1 = fmaxf(mx1, __shfl_xor_sync(0xffffffffu, mx1, 1));
            mx1 = fmaxf(mx1, __shfl_xor_sync(0xffffffffu, mx1, 2));

            const float mn0 = fmaxf(mrow0, mx0);
            const float mn1 = fmaxf(mrow1, mx1);
            const float al0 = exp2f(mrow0 - mn0);
            const float al1 = exp2f(mrow1 - mn1);
            float sum0 = 0.0f;
            float sum1 = 0.0f;
#pragma unroll
            for (int j = 0; j < 4; j++) {
                const float p0 = exp2f(s[j][0] - mn0);
                const float p1 = exp2f(s[j][1] - mn0);
                const float p2 = exp2f(s[j][2] - mn1);
                const float p3 = exp2f(s[j][3] - mn1);
                s[j][0] = p0;
                s[j][1] = p1;
                s[j][2] = p2;
                s[j][3] = p3;
                sum0 += p0 + p1;
                sum1 += p2 + p3;
            }
            sum0 += __shfl_xor_sync(0xffffffffu, sum0, 1);
            sum0 += __shfl_xor_sync(0xffffffffu, sum0, 2);
            sum1 += __shfl_xor_sync(0xffffffffu, sum1, 1);
            sum1 += __shfl_xor_sync(0xffffffffu, sum1, 2);
            lrow0 = lrow0 * al0 + sum0;
            lrow1 = lrow1 * al1 + sum1;
            mrow0 = mn0;
            mrow1 = mn1;
#pragma unroll
            for (int j = 0; j < 8; j++) {
                o[j][0] *= al0;
                o[j][1] *= al0;
                o[j][2] *= al1;
                o[j][3] *= al1;
            }
        }

        // O += P @ V  (P fp16, V hi only), 32 keys
#pragma unroll
        for (int kk = 0; kk < 2; kk++) {
            u32 pa[4];
            pa[0] = packf2(s[2 * kk + 0][0], s[2 * kk + 0][1]);
            pa[1] = packf2(s[2 * kk + 0][2], s[2 * kk + 0][3]);
            pa[2] = packf2(s[2 * kk + 1][0], s[2 * kk + 1][1]);
            pa[3] = packf2(s[2 * kk + 1][2], s[2 * kk + 1][3]);
#pragma unroll
            for (int jd = 0; jd < 4; jd++) {
                u32 vh4[4];
                const u32 off = (u32)((kk * 16 + vrow) * ALD + jd * 16 + vcol) * 2u;
                ldsm4t(vh4, tb + 2 * AARR + off);
                mma16816(o[jd * 2 + 0], pa, &vh4[0]);
                mma16816(o[jd * 2 + 1], pa, &vh4[2]);
            }
        }
    }

    // epilogue: normalize, store AO (hi only)
    const int bb = bh >> 4;
    const int hh = bh & 15;
    const float il0 = 1.0f / lrow0;
    const float il1 = 1.0f / lrow1;
    const int qa = q0 + wid * 16 + g;
    const size_t rowa = ((size_t)bb * S_ + qa) * DM_ + hh * HD_;
    const size_t rowb = ((size_t)bb * S_ + qa + 8) * DM_ + hh * HD_;
#pragma unroll
    for (int j = 0; j < 8; j++) {
        const int dd = j * 8 + t * 2;
        const float v0 = o[j][0] * il0;
        const float v1 = o[j][1] * il0;
        const float v2 = o[j][2] * il1;
        const float v3 = o[j][3] * il1;
        *(__half2*)&g_AOhi[rowa + dd] =
            __halves2half2(__float2half_rn(v0), __float2half_rn(v1));
        *(__half2*)&g_AOhi[rowb + dd] =
            __halves2half2(__float2half_rn(v2), __float2half_rn(v3));
    }
}

// ---------------------------------------------------------------------------
extern "C" void kernel_launch(void* const* d_in, const int* in_sizes, int n_in,
                              void* d_out, int out_size)
{
    const float* x  = (const float*)d_in[0];
    const int*   tp = (const int*)d_in[1];
    const float* Wq = (const float*)d_in[2];
    const float* Wk = (const float*)d_in[3];
    const float* Wv = (const float*)d_in[4];
    const float* Wo = (const float*)d_in[5];
    float* out = (float*)d_out;

    static int attr_done = 0;
    if (!attr_done) {
        cudaFuncSetAttribute(hgemm_kernel<0>,
                             cudaFuncAttributeMaxDynamicSharedMemorySize, GSMEM);
        cudaFuncSetAttribute(hgemm_kernel<1>,
                             cudaFuncAttributeMaxDynamicSharedMemorySize, GSMEM);
        attr_done = 1;
    }

    rope_table_kernel<<<256, 256>>>(tp);
    split_x_kernel<<<512, 256>>>(x);
    {
        dim3 grid(128, 4);
        split_w_kernel<<<grid, 256>>>(Wq, Wk, Wv, Wo);
    }
    {
        dim3 grid(DM_ / 128, M_ / 128, 3);
        hgemm_kernel<0><<<grid, 256, GSMEM>>>(nullptr);
    }
    {
        dim3 grid(S_ / 64, B_ * H_);
        attn_kernel<<<grid, 128>>>();
    }
    {
        dim3 grid(DM_ / 128, M_ / 128, 1);
        hgemm_kernel<1><<<grid, 256, GSMEM>>>(out);
    }
}

// round 16
// speedup vs baseline: 1.4319x; 1.1075x over previous
#include <cuda_runtime.h>
#include <cuda_fp16.h>
#include <stdint.h>
#include <math.h>
#include <float.h>

typedef unsigned int u32;

#define B_   2
#define S_   2048
#define H_   16
#define HD_  64
#define DM_  1024
#define M_   (B_ * S_)

// ---------------- device scratch (no allocations allowed) ------------------
__device__ __half g_Xhi[(size_t)M_ * DM_];
__device__ __half g_Whi[(size_t)4 * DM_ * DM_];
__device__ __half g_Wlo[(size_t)4 * DM_ * DM_];
__device__ __half g_Qhi[(size_t)M_ * DM_];   // [b,h,s,d], pre-scaled by 0.125*log2(e)
__device__ __half g_Qlo[(size_t)M_ * DM_];
__device__ __half g_Khi[(size_t)M_ * DM_];
__device__ __half g_Klo[(size_t)M_ * DM_];
__device__ __half g_Vhi[(size_t)M_ * DM_];
__device__ __half g_AOhi[(size_t)M_ * DM_];
__device__ float  g_rcos[(size_t)S_ * 32];
__device__ float  g_rsin[(size_t)S_ * 32];

// ---------------- PTX helpers ----------------------------------------------
__device__ __forceinline__ u32 s2u(const void* p)
{
    u32 a;
    asm("{ .reg .u64 t; cvta.to.shared.u64 t, %1; cvt.u32.u64 %0, t; }"
        : "=r"(a) : "l"(p));
    return a;
}

__device__ __forceinline__ void ldsm4(u32* r, u32 addr)
{
    asm volatile("ldmatrix.sync.aligned.m8n8.x4.shared.b16 {%0,%1,%2,%3},[%4];"
                 : "=r"(r[0]), "=r"(r[1]), "=r"(r[2]), "=r"(r[3]) : "r"(addr));
}

__device__ __forceinline__ void ldsm4t(u32* r, u32 addr)
{
    asm volatile("ldmatrix.sync.aligned.m8n8.x4.trans.shared.b16 {%0,%1,%2,%3},[%4];"
                 : "=r"(r[0]), "=r"(r[1]), "=r"(r[2]), "=r"(r[3]) : "r"(addr));
}

__device__ __forceinline__ void mma16816(float* c, const u32* a, const u32* b)
{
    asm volatile("mma.sync.aligned.m16n8k16.row.col.f32.f16.f16.f32 "
                 "{%0,%1,%2,%3},{%4,%5,%6,%7},{%8,%9},{%0,%1,%2,%3};"
                 : "+f"(c[0]), "+f"(c[1]), "+f"(c[2]), "+f"(c[3])
                 : "r"(a[0]), "r"(a[1]), "r"(a[2]), "r"(a[3]),
                   "r"(b[0]), "r"(b[1]));
}

__device__ __forceinline__ u32 packf2(float lo, float hi)
{
    u32 u;
    asm("cvt.rn.f16x2.f32 %0, %1, %2;" : "=r"(u) : "f"(hi), "f"(lo));
    return u;
}

__device__ __forceinline__ void cpa16(u32 saddr, const void* gaddr)
{
    asm volatile("cp.async.cg.shared.global [%0], [%1], 16;"
                 :: "r"(saddr), "l"(gaddr));
}

__device__ __forceinline__ void cp_commit()
{
    asm volatile("cp.async.commit_group;" ::: "memory");
}

__device__ __forceinline__ void cp_wait1()
{
    asm volatile("cp.async.wait_group 1;" ::: "memory");
}

__device__ __forceinline__ void cp_wait0()
{
    asm volatile("cp.async.wait_group 0;" ::: "memory");
}

__device__ __forceinline__ u32 swz64(u32 b)
{
    return b ^ ((b >> 3) & 0x30u);
}

// ---------------- fp32 -> fp16 splitters ------------------------------------
__global__ __launch_bounds__(256) void split_x_kernel(const float* __restrict__ src)
{
    const int n = M_ * DM_;
    for (int i = (blockIdx.x * blockDim.x + threadIdx.x) * 4; i < n;
         i += gridDim.x * blockDim.x * 4) {
        float4 v = *(const float4*)&src[i];
        ((__half2*)&g_Xhi[i])[0] = __halves2half2(__float2half_rn(v.x), __float2half_rn(v.y));
        ((__half2*)&g_Xhi[i])[1] = __halves2half2(__float2half_rn(v.z), __float2half_rn(v.w));
    }
}

__global__ __launch_bounds__(256) void split_w_kernel(const float* __restrict__ w0,
                                                      const float* __restrict__ w1,
                                                      const float* __restrict__ w2,
                                                      const float* __restrict__ w3)
{
    const int which = blockIdx.y;
    const float* src = (which == 0) ? w0 : ((which == 1) ? w1 : ((which == 2) ? w2 : w3));
    __half* dh = g_Whi + (size_t)which * (DM_ * DM_);
    __half* dl = g_Wlo + (size_t)which * (DM_ * DM_);
    const int n = DM_ * DM_;
    for (int i = (blockIdx.x * blockDim.x + threadIdx.x) * 4; i < n;
         i += gridDim.x * blockDim.x * 4) {
        float4 v = *(const float4*)&src[i];
        __half h0 = __float2half_rn(v.x);
        __half h1 = __float2half_rn(v.y);
        __half h2 = __float2half_rn(v.z);
        __half h3 = __float2half_rn(v.w);
        __half l0 = __float2half_rn(v.x - __half2float(h0));
        __half l1 = __float2half_rn(v.y - __half2float(h1));
        __half l2 = __float2half_rn(v.z - __half2float(h2));
        __half l3 = __float2half_rn(v.w - __half2float(h3));
        ((__half2*)&dh[i])[0] = __halves2half2(h0, h1);
        ((__half2*)&dh[i])[1] = __halves2half2(h2, h3);
        ((__half2*)&dl[i])[0] = __halves2half2(l0, l1);
        ((__half2*)&dl[i])[1] = __halves2half2(l2, l3);
    }
}

// ---------------- RoPE cos/sin table (one-shot) -----------------------------
__global__ __launch_bounds__(256) void rope_table_kernel(const int* __restrict__ tpos)
{
    const int i = blockIdx.x * blockDim.x + threadIdx.x;   // 0..65535
    if (i >= S_ * 32) return;
    const int s  = i >> 5;
    const int d2 = i & 31;
    const float pos = (float)tpos[s];
    const float inv = expf(-(float)(2 * d2) * 0.14391156931f);  // ln(10000)/64
    float sn, cs;
    sincosf(pos * inv, &sn, &cs);
    g_rcos[i] = cs;
    g_rsin[i] = sn;
}

// ---------------- fp16 GEMM: A_hi x (W_hi + W_lo) ---------------------------
// Y[m,n] = sum_k A[m,k] * W[n,k]; fp32 acc; combos hh + hl.
// Block 128x128, 8 warps (2m x 4n), warp tile 64x32.
// SW64-swizzled smem (64B rows), 3 stages, ONE barrier per stage.
// __launch_bounds__(256,2): cap regs at 128 so 2 CTAs co-reside per SM.
#define GARR  8192                     // bytes per array per stage (128 x 64B)
#define GOFF_BHI  GARR
#define GOFF_BLO  (2 * GARR)
#define GSSB  (3 * GARR)               // stage stride = 24576
#define GSMEM (3 * GSSB)               // 73728

__device__ __forceinline__ void gemm_stage_load(u32 sb, int st, int tid,
                                                int m0, int n0, int k0,
                                                const __half* A,
                                                const __half* Bh, const __half* Bl)
{
#pragma unroll
    for (int u = 0; u < 2; u++) {
        const int id  = tid * 2 + u;      // 0..511
        const int row = id >> 2;          // 0..127
        const int c16 = id & 3;           // 16B chunk
        const u32 so  = sb + (u32)(st * GSSB) + swz64((u32)(row * 64 + c16 * 16));
        const size_t ga = (size_t)(m0 + row) * DM_ + k0 + c16 * 8;
        const size_t gb = (size_t)(n0 + row) * DM_ + k0 + c16 * 8;
        cpa16(so,            &A[ga]);
        cpa16(so + GOFF_BHI, &Bh[gb]);
        cpa16(so + GOFF_BLO, &Bl[gb]);
    }
}

template <int MODE>
__global__ __launch_bounds__(256, 2) void hgemm_kernel(float* __restrict__ outp)
{
    extern __shared__ __half gsm[];

    const int z = (MODE == 0) ? blockIdx.z : 3;
    const __half* A  = (MODE == 0) ? g_Xhi : g_AOhi;
    const __half* Bh = g_Whi + (size_t)z * DM_ * DM_;
    const __half* Bl = g_Wlo + (size_t)z * DM_ * DM_;

    const int tid  = threadIdx.x;
    const int lane = tid & 31;
    const int wid  = tid >> 5;
    const int wm   = wid >> 2;
    const int wn   = wid & 3;
    const int m0   = blockIdx.y * 128;
    const int n0   = blockIdx.x * 128;

    const u32 sb = s2u(gsm);

    float acc[4][4][4];
#pragma unroll
    for (int i = 0; i < 4; i++) {
#pragma unroll
        for (int j = 0; j < 4; j++) {
            acc[i][j][0] = 0.0f; acc[i][j][1] = 0.0f;
            acc[i][j][2] = 0.0f; acc[i][j][3] = 0.0f;
        }
    }

    const int arow = wm * 64 + (lane & 15);
    const int acol = (lane >> 4) << 3;
    const int brow = wn * 32 + (lane & 7) + ((lane & 16) ? 8 : 0);
    const int bcol = (lane & 8) ? 8 : 0;

    gemm_stage_load(sb, 0, tid, m0, n0, 0, A, Bh, Bl);
    cp_commit();
    gemm_stage_load(sb, 1, tid, m0, n0, 32, A, Bh, Bl);
    cp_commit();

    for (int it = 0; it < 32; it++) {
        if (it < 31) {
            cp_wait1();
        } else {
            cp_wait0();
        }
        __syncthreads();      // stage it visible; compute of it-1 done by all

        if (it < 30) {
            gemm_stage_load(sb, (it + 2) % 3, tid, m0, n0, (it + 2) * 32,
                            A, Bh, Bl);
            cp_commit();
        }

        const u32 tb = sb + (u32)((it % 3) * GSSB);

#pragma unroll
        for (int ks = 0; ks < 32; ks += 16) {
            u32 ah[4][4];
            u32 bh2[2][4];
            u32 bl2[2][4];
#pragma unroll
            for (int i = 0; i < 4; i++) {
                const u32 off = swz64((u32)((arow + i * 16) * 64 + (ks + acol) * 2));
                ldsm4(ah[i], tb + off);
            }
#pragma unroll
            for (int jn = 0; jn < 2; jn++) {
                const u32 off = swz64((u32)((brow + jn * 16) * 64 + (ks + bcol) * 2));
                ldsm4(bh2[jn], tb + GOFF_BHI + off);
                ldsm4(bl2[jn], tb + GOFF_BLO + off);
            }
#pragma unroll
            for (int i = 0; i < 4; i++) {
#pragma unroll
                for (int j = 0; j < 4; j++) {
                    const u32* Bhf = &bh2[j >> 1][(j & 1) * 2];
                    const u32* Blf = &bl2[j >> 1][(j & 1) * 2];
                    mma16816(acc[i][j], ah[i], Bhf);
                    mma16816(acc[i][j], ah[i], Blf);
                }
            }
        }
    }

    const int g = lane >> 2;
    const int t = lane & 3;

    if (MODE == 1) {
#pragma unroll
        for (int i = 0; i < 4; i++) {
            const int m = m0 + wm * 64 + i * 16 + g;
#pragma unroll
            for (int j = 0; j < 4; j++) {
                const int n = n0 + wn * 32 + j * 8 + t * 2;
                *(float2*)&outp[(size_t)m * DM_ + n] = make_float2(acc[i][j][0], acc[i][j][1]);
                *(float2*)&outp[(size_t)(m + 8) * DM_ + n] = make_float2(acc[i][j][2], acc[i][j][3]);
            }
        }
        return;
    }

    // MODE 0 epilogue: RoPE via table (z<2), scale (z==0), hi/lo split (Q,K),
    // V (z==2) hi only.
    __half* Dhi = (z == 0) ? g_Qhi : ((z == 1) ? g_Khi : g_Vhi);
    __half* Dlo = (z == 0) ? g_Qlo : g_Klo;   // unused for z==2
    const float qscale = 0.18033688011f;      // 0.125 * log2(e)
#pragma unroll
    for (int i = 0; i < 4; i++) {
#pragma unroll
        for (int rr = 0; rr < 2; rr++) {
            const int m = m0 + wm * 64 + i * 16 + g + rr * 8;
            const int bb = m >> 11;
            const int ss = m & (S_ - 1);
#pragma unroll
            for (int j = 0; j < 4; j++) {
                const int n = n0 + wn * 32 + j * 8 + t * 2;
                const int hh = n >> 6;
                const int dd = n & 63;
                float v0 = acc[i][j][rr * 2 + 0];
                float v1 = acc[i][j][rr * 2 + 1];
                if (z < 2) {
                    const int ridx = ss * 32 + (dd >> 1);
                    const float cs = g_rcos[ridx];
                    const float sn = g_rsin[ridx];
                    const float r1 = v0 * cs - v1 * sn;
                    const float r2 = v0 * sn + v1 * cs;
                    v0 = r1;
                    v1 = r2;
                }
                if (z == 0) {
                    v0 *= qscale;
                    v1 *= qscale;
                }
                const __half p0 = __float2half_rn(v0);
                const __half p1 = __float2half_rn(v1);
                const size_t ofs = ((size_t)(bb * H_ + hh) * S_ + ss) * HD_ + dd;
                *(__half2*)&Dhi[ofs] = __halves2half2(p0, p1);
                if (z < 2) {
                    const __half e0 = __float2half_rn(v0 - __half2float(p0));
                    const __half e1 = __float2half_rn(v1 - __half2float(p1));
                    *(__half2*)&Dlo[ofs] = __halves2half2(e0, e1);
                }
            }
        }
    }
}

// ---------------- mma flash attention (causal), 3-stage single-barrier ------
// 32-key tiles; stage = [Kh][Kl][Vh] 13.8 KB; 3 stages (41.5 KB static).
#define ALD  72
#define AARR (32 * ALD * 2)        // 4608 bytes
#define ASTG (3 * AARR)            // 13824 bytes per stage

__device__ __forceinline__ void attn_stage_load(u32 sb, int st, int tid,
                                                size_t gbase, int k0)
{
#pragma unroll
    for (int u = 0; u < 2; u++) {
        const int id  = tid * 2 + u;      // 0..255
        const int row = id >> 3;          // 0..31
        const int c   = (id & 7) * 8;     // 0..56
        const size_t go = gbase + (size_t)(k0 + row) * HD_ + c;
        const u32 so = sb + (u32)(st * ASTG) + (u32)(row * ALD + c) * 2u;
        cpa16(so,            &g_Khi[go]);
        cpa16(so + AARR,     &g_Klo[go]);
        cpa16(so + 2 * AARR, &g_Vhi[go]);
    }
}

__global__ __launch_bounds__(128) void attn_kernel()
{
    __shared__ __half smem[3 * ASTG / 2];   // 41472 bytes

    const int tid  = threadIdx.x;
    const int lane = tid & 31;
    const int wid  = tid >> 5;
    const int q0   = (gridDim.x - 1 - blockIdx.x) * 64;   // long blocks first
    const int bh   = blockIdx.y;
    const size_t gbase = (size_t)bh * S_ * HD_;

    const u32 sb = s2u(smem);

    // ---- stage Q tile (hi at 0, lo at 64*ALD) and pull fragments ----
    for (int u = tid; u < 512; u += 128) {
        const int row = u >> 3;
        const int c   = (u & 7) * 8;
        *(int4*)&smem[row * ALD + c] =
            *(const int4*)&g_Qhi[gbase + (size_t)(q0 + row) * HD_ + c];
        *(int4*)&smem[64 * ALD + row * ALD + c] =
            *(const int4*)&g_Qlo[gbase + (size_t)(q0 + row) * HD_ + c];
    }
    __syncthreads();

    u32 qh[4][4];
    u32 ql[4][4];
    {
        const int row = wid * 16 + (lane & 15);
        const int col = (lane >> 4) << 3;
        const u32 qlo_off = (u32)(64 * ALD) * 2u;
#pragma unroll
        for (int kd = 0; kd < 4; kd++) {
            const u32 off = (u32)(row * ALD + kd * 16 + col) * 2u;
            ldsm4(qh[kd], sb + off);
            ldsm4(ql[kd], sb + qlo_off + off);
        }
    }
    __syncthreads();

    float o[8][4];
#pragma unroll
    for (int j = 0; j < 8; j++) {
        o[j][0] = 0.0f; o[j][1] = 0.0f; o[j][2] = 0.0f; o[j][3] = 0.0f;
    }
    float mrow0 = -1e30f;
    float mrow1 = -1e30f;
    float lrow0 = 0.0f;
    float lrow1 = 0.0f;

    const int g = lane >> 2;
    const int t = lane & 3;
    const int browK = (lane & 7) + ((lane & 16) ? 8 : 0);
    const int bcolK = (lane & 8) ? 8 : 0;
    const int vrow  = lane & 15;
    const int vcol  = (lane >> 4) << 3;

    const int ntiles = q0 / 32 + 2;     // keys 0 .. q0+63 (ntiles >= 2)

    attn_stage_load(sb, 0, tid, gbase, 0);
    cp_commit();
    attn_stage_load(sb, 1, tid, gbase, 32);
    cp_commit();

    for (int it = 0; it < ntiles; it++) {
        const int k0 = it * 32;
        if (it < ntiles - 1) {
            cp_wait1();
        } else {
            cp_wait0();
        }
        __syncthreads();      // stage it visible; compute of it-1 done by all

        if (it + 2 < ntiles) {
            attn_stage_load(sb, (it + 2) % 3, tid, gbase, (it + 2) * 32);
            cp_commit();
        }

        const u32 tb = sb + (u32)((it % 3) * ASTG);

        // S = Q K^T over 32 keys (Q pre-scaled by 0.125*log2e -> base-2 space)
        float s[4][4];
#pragma unroll
        for (int j = 0; j < 4; j++) {
            s[j][0] = 0.0f; s[j][1] = 0.0f; s[j][2] = 0.0f; s[j][3] = 0.0f;
        }
#pragma unroll
        for (int kd = 0; kd < 4; kd++) {
#pragma unroll
            for (int jn = 0; jn < 2; jn++) {
                u32 kh4[4];
                u32 kl4[4];
                const u32 off = (u32)((jn * 16 + browK) * ALD + kd * 16 + bcolK) * 2u;
                ldsm4(kh4, tb + off);
                ldsm4(kl4, tb + AARR + off);
                mma16816(s[jn * 2 + 0], qh[kd], &kh4[0]);
                mma16816(s[jn * 2 + 0], qh[kd], &kl4[0]);
                mma16816(s[jn * 2 + 0], ql[kd], &kh4[0]);
                mma16816(s[jn * 2 + 1], qh[kd], &kh4[2]);
                mma16816(s[jn * 2 + 1], qh[kd], &kl4[2]);
                mma16816(s[jn * 2 + 1], ql[kd], &kh4[2]);
            }
        }

        // causal mask (last two tiles only)
        if (k0 + 32 > q0) {
#pragma unroll
            for (int j = 0; j < 4; j++) {
#pragma unroll
                for (int e = 0; e < 4; e++) {
                    const int kidx = k0 + j * 8 + t * 2 + (e & 1);
                    const int qidx = q0 + wid * 16 + g + (e >> 1) * 8;
                    if (kidx > qidx) s[j][e] = -1e30f;
                }
            }
        }

        // online softmax (base 2), row pair (g, g+8)
        {
            float mx0 = -1e30f;
            float mx1 = -1e30f;
#pragma unroll
            for (int j = 0; j < 4; j++) {
                mx0 = fmaxf(mx0, fmaxf(s[j][0], s[j][1]));
                mx1 = fmaxf(mx1, fmaxf(s[j][2], s[j][3]));
            }
            mx0 = fmaxf(mx0, __shfl_xor_sync(0xffffffffu, mx0, 1));
            mx0 = fmaxf(mx0, __shfl_xor_sync(0xffffffffu, mx0, 2));
            mx1 = fmaxf(mx1, __shfl_xor_sync(0xffffffffu, mx1, 1));
            mx1 = fmaxf(mx1, __shfl_xor_sync(0xffffffffu, mx1, 2));

            const float mn0 = fmaxf(mrow0, mx0);
            const float mn1 = fmaxf(mrow1, mx1);
            const float al0 = exp2f(mrow0 - mn0);
            const float al1 = exp2f(mrow1 - mn1);
            float sum0 = 0.0f;
            float sum1 = 0.0f;
#pragma unroll
            for (int j = 0; j < 4; j++) {
                const float p0 = exp2f(s[j][0] - mn0);
                const float p1 = exp2f(s[j][1] - mn0);
                const float p2 = exp2f(s[j][2] - mn1);
                const float p3 = exp2f(s[j][3] - mn1);
                s[j][0] = p0;
                s[j][1] = p1;
                s[j][2] = p2;
                s[j][3] = p3;
                sum0 += p0 + p1;
                sum1 += p2 + p3;
            }
            sum0 += __shfl_xor_sync(0xffffffffu, sum0, 1);
            sum0 += __shfl_xor_sync(0xffffffffu, sum0, 2);
            sum1 += __shfl_xor_sync(0xffffffffu, sum1, 1);
            sum1 += __shfl_xor_sync(0xffffffffu, sum1, 2);
            lrow0 = lrow0 * al0 + sum0;
            lrow1 = lrow1 * al1 + sum1;
            mrow0 = mn0;
            mrow1 = mn1;
#pragma unroll
            for (int j = 0; j < 8; j++) {
                o[j][0] *= al0;
                o[j][1] *= al0;
                o[j][2] *= al1;
                o[j][3] *= al1;
            }
        }

        // O += P @ V  (P fp16, V hi only), 32 keys
#pragma unroll
        for (int kk = 0; kk < 2; kk++) {
            u32 pa[4];
            pa[0] = packf2(s[2 * kk + 0][0], s[2 * kk + 0][1]);
            pa[1] = packf2(s[2 * kk + 0][2], s[2 * kk + 0][3]);
            pa[2] = packf2(s[2 * kk + 1][0], s[2 * kk + 1][1]);
            pa[3] = packf2(s[2 * kk + 1][2], s[2 * kk + 1][3]);
#pragma unroll
            for (int jd = 0; jd < 4; jd++) {
                u32 vh4[4];
                const u32 off = (u32)((kk * 16 + vrow) * ALD + jd * 16 + vcol) * 2u;
                ldsm4t(vh4, tb + 2 * AARR + off);
                mma16816(o[jd * 2 + 0], pa, &vh4[0]);
                mma16816(o[jd * 2 + 1], pa, &vh4[2]);
            }
        }
    }

    // epilogue: normalize, store AO (hi only)
    const int bb = bh >> 4;
    const int hh = bh & 15;
    const float il0 = 1.0f / lrow0;
    const float il1 = 1.0f / lrow1;
    const int qa = q0 + wid * 16 + g;
    const size_t rowa = ((size_t)bb * S_ + qa) * DM_ + hh * HD_;
    const size_t rowb = ((size_t)bb * S_ + qa + 8) * DM_ + hh * HD_;
#pragma unroll
    for (int j = 0; j < 8; j++) {
        const int dd = j * 8 + t * 2;
        const float v0 = o[j][0] * il0;
        const float v1 = o[j][1] * il0;
        const float v2 = o[j][2] * il1;
        const float v3 = o[j][3] * il1;
        *(__half2*)&g_AOhi[rowa + dd] =
            __halves2half2(__float2half_rn(v0), __float2half_rn(v1));
        *(__half2*)&g_AOhi[rowb + dd] =
            __halves2half2(__float2half_rn(v2), __float2half_rn(v3));
    }
}

// ---------------------------------------------------------------------------
extern "C" void kernel_launch(void* const* d_in, const int* in_sizes, int n_in,
                              void* d_out, int out_size)
{
    const float* x  = (const float*)d_in[0];
    const int*   tp = (const int*)d_in[1];
    const float* Wq = (const float*)d_in[2];
    const float* Wk = (const float*)d_in[3];
    const float* Wv = (const float*)d_in[4];
    const float* Wo = (const float*)d_in[5];
    float* out = (float*)d_out;

    static int attr_done = 0;
    if (!attr_done) {
        cudaFuncSetAttribute(hgemm_kernel<0>,
                             cudaFuncAttributeMaxDynamicSharedMemorySize, GSMEM);
        cudaFuncSetAttribute(hgemm_kernel<1>,
                             cudaFuncAttributeMaxDynamicSharedMemorySize, GSMEM);
        attr_done = 1;
    }

    rope_table_kernel<<<256, 256>>>(tp);
    split_x_kernel<<<512, 256>>>(x);
    {
        dim3 grid(128, 4);
        split_w_kernel<<<grid, 256>>>(Wq, Wk, Wv, Wo);
    }
    {
        dim3 grid(DM_ / 128, M_ / 128, 3);
        hgemm_kernel<0><<<grid, 256, GSMEM>>>(nullptr);
    }
    {
        dim3 grid(S_ / 64, B_ * H_);
        attn_kernel<<<grid, 128>>>();
    }
    {
        dim3 grid(DM_ / 128, M_ / 128, 1);
        hgemm_kernel<1><<<grid, 256, GSMEM>>>(out);
    }
}